// round 12
// baseline (speedup 1.0000x reference)
#include <cuda_runtime.h>
#include <cuda_fp16.h>
#include <mma.h>
#include <math.h>

using namespace nvcuda;

#define NN 20000
#define FEAT 128
#define HID 32
#define HEADS 8
#define HC 256          // HEADS*HID
#define CLS 40
#define CLSP 64         // padded cols for tensor GEMM2
#define E_IN 640000
#define TOT (E_IN + NN)
#define NEG 0.2f
#define NB ((NN + 255) / 256)   // 79 scan blocks

// ---------------- scratch (device globals; no allocation allowed) ----------------
__device__ __half g_xh[NN * FEAT];     // x in fp16
__device__ __half g_w1h[FEAT * HC];    // W1 in fp16
__device__ __half g_w2h[HC * CLSP];    // W2 in fp16, zero-padded to 64 cols
__device__ __half g_h1h[NN * HC];      // layer1 linear output (fp16, for gather)
__device__ __half g_h2h[NN * HC];      // layer1 GAT output after ELU (fp16)
__device__ float  g_as1[NN * HEADS];
__device__ float  g_ad1[NN * HEADS];
__device__ float  g_g2[NN * CLS];      // layer2 linear output (fp32)
__device__ __half g_g2h[NN * CLS];     // layer2 linear output (fp16, for gather)
__device__ float  g_as2[NN];
__device__ float  g_ad2[NN];
__device__ int    g_rowptr[NN + 1];
__device__ int    g_cnt[NN];
__device__ int    g_cur[NN];
__device__ int    g_bsum[128];
__device__ int    g_boff[128];
__device__ int    g_esrc[TOT];         // src node per CSR slot (sorted by dst)

// ---------------- helpers (edge_index is INT32; loads always in-bounds) ----------------
__device__ __forceinline__ int edge_src(const int* ei, int e) {
    int idx = (e < E_IN) ? e : 0;
    int v = ei[idx];
    return (e < E_IN) ? v : (e - E_IN);
}
__device__ __forceinline__ int edge_dst(const int* ei, int e) {
    int idx = (e < E_IN) ? (E_IN + e) : 0;
    int v = ei[idx];
    return (e < E_IN) ? v : (e - E_IN);
}
__device__ __forceinline__ float lrelu(float v) { return v > 0.0f ? v : NEG * v; }

// ---------------- init + fp16 conversion ----------------
__global__ void k_init() {
    int t = blockIdx.x * blockDim.x + threadIdx.x;
    if (t < NN) g_cnt[t] = 0;
}

__global__ void k_cvt(const float* __restrict__ x, const float* __restrict__ W1,
                      const float* __restrict__ W2) {
    int t = blockIdx.x * blockDim.x + threadIdx.x;
    const int NX = NN * FEAT / 2;           // half2 units of x
    const int NW = FEAT * HC / 2;           // half2 units of W1
    const int NW2 = HC * CLSP / 2;          // half2 units of padded W2
    if (t < NX) {
        float2 v = *(const float2*)&x[t * 2];
        *(__half2*)&g_xh[t * 2] = __float22half2_rn(v);
    } else if (t < NX + NW) {
        int u = t - NX;
        float2 v = *(const float2*)&W1[u * 2];
        *(__half2*)&g_w1h[u * 2] = __float22half2_rn(v);
    } else if (t < NX + NW + NW2) {
        int u = t - NX - NW;
        int row = u / (CLSP / 2);
        int cp = (u % (CLSP / 2)) * 2;
        float v0 = (cp < CLS) ? W2[row * CLS + cp] : 0.0f;
        float v1 = (cp + 1 < CLS) ? W2[row * CLS + cp + 1] : 0.0f;
        *(__half2*)&g_w2h[u * 2] = __float22half2_rn(make_float2(v0, v1));
    }
}

// ---------------- CSR build ----------------
__global__ void k_count(const int* __restrict__ ei) {
    int t = blockIdx.x * blockDim.x + threadIdx.x;
    int e0 = t * 4;
    if (e0 >= TOT) return;
    if (e0 + 3 < E_IN) {
        int4 d4 = *(const int4*)&ei[E_IN + e0];
        atomicAdd(&g_cnt[d4.x], 1);
        atomicAdd(&g_cnt[d4.y], 1);
        atomicAdd(&g_cnt[d4.z], 1);
        atomicAdd(&g_cnt[d4.w], 1);
    } else {
        for (int k = 0; k < 4 && e0 + k < TOT; k++)
            atomicAdd(&g_cnt[edge_dst(ei, e0 + k)], 1);
    }
}

// Multi-block scan, phase 1: per-block sums of 256 counts
__global__ void k_bsum() {
    __shared__ int sm[256];
    int t = threadIdx.x;
    int i = blockIdx.x * 256 + t;
    int v = (i < NN) ? g_cnt[i] : 0;
    sm[t] = v;
    __syncthreads();
    for (int off = 128; off; off >>= 1) {
        if (t < off) sm[t] += sm[t + off];
        __syncthreads();
    }
    if (t == 0) g_bsum[blockIdx.x] = sm[0];
}

// phase 2: scan NB block sums (single block of 128)
__global__ void k_bscan() {
    __shared__ int sm[128];
    int t = threadIdx.x;
    int v = (t < NB) ? g_bsum[t] : 0;
    sm[t] = v;
    __syncthreads();
    for (int off = 1; off < 128; off <<= 1) {
        int idx = (t >= off) ? (t - off) : t;
        int add = sm[idx];
        if (t < off) add = 0;
        __syncthreads();
        sm[t] += add;
        __syncthreads();
    }
    if (t < NB) g_boff[t] = sm[t] - v;     // exclusive
    if (t == 127) g_rowptr[NN] = sm[127];
}

// phase 3: per-block exclusive scan + global offset -> rowptr/cur
__global__ void k_writeptr() {
    __shared__ int sm[256];
    int t = threadIdx.x;
    int i = blockIdx.x * 256 + t;
    int v = (i < NN) ? g_cnt[i] : 0;
    sm[t] = v;
    __syncthreads();
    for (int off = 1; off < 256; off <<= 1) {
        int idx = (t >= off) ? (t - off) : t;
        int add = sm[idx];
        if (t < off) add = 0;
        __syncthreads();
        sm[t] += add;
        __syncthreads();
    }
    if (i < NN) {
        int excl = sm[t] - v + g_boff[blockIdx.x];
        g_rowptr[i] = excl;
        g_cur[i] = excl;
    }
}

__global__ void k_scatter(const int* __restrict__ ei) {
    int t = blockIdx.x * blockDim.x + threadIdx.x;
    if (t >= TOT) return;
    int d = edge_dst(ei, t);
    int s = edge_src(ei, t);
    int pos = atomicAdd(&g_cur[d], 1);
    g_esrc[pos] = s;
}

// ---------------- GEMM1 (tensor core): xh @ W1h -> g_h1h + fused alpha1 ----------------
__global__ __launch_bounds__(256) void k_gemm1(const float* __restrict__ a1s,
                                               const float* __restrict__ a1d) {
    const int BM = 128, BN = 64, BK = 32;
    const int LDA = BK + 8;
    const int LDB = BN + 8;
    const int LDC = BN + 8;
    __shared__ __align__(16) __half Ah[BM * LDA];
    __shared__ __align__(16) __half Bh[BK * LDB];
    __shared__ __align__(16) float  Cs[BM * LDC];

    int tid = threadIdx.x;
    int wid = tid >> 5;
    int row0 = blockIdx.x * BM;
    int col0 = blockIdx.y * BN;
    int wm = (wid & 3) * 32;
    int wn = (wid >> 2) * 32;

    wmma::fragment<wmma::accumulator, 16, 16, 16, float> acc[2][2];
#pragma unroll
    for (int i = 0; i < 2; i++)
#pragma unroll
        for (int j = 0; j < 2; j++)
            wmma::fill_fragment(acc[i][j], 0.0f);

    for (int k0 = 0; k0 < FEAT; k0 += BK) {
#pragma unroll
        for (int q = 0; q < 2; q++) {
            int li = tid * 2 + q;
            int r = li >> 2;
            int c8 = li & 3;
            int gr = row0 + r;
            if (gr > NN - 1) gr = NN - 1;
            *(uint4*)&Ah[r * LDA + c8 * 8] = *(const uint4*)&g_xh[gr * FEAT + k0 + c8 * 8];
        }
        {
            int r = tid >> 3;
            int c8 = tid & 7;
            *(uint4*)&Bh[r * LDB + c8 * 8] = *(const uint4*)&g_w1h[(k0 + r) * HC + col0 + c8 * 8];
        }
        __syncthreads();
#pragma unroll
        for (int kk = 0; kk < BK; kk += 16) {
            wmma::fragment<wmma::matrix_a, 16, 16, 16, __half, wmma::row_major> af[2];
            wmma::fragment<wmma::matrix_b, 16, 16, 16, __half, wmma::row_major> bf[2];
#pragma unroll
            for (int i = 0; i < 2; i++)
                wmma::load_matrix_sync(af[i], &Ah[(wm + i * 16) * LDA + kk], LDA);
#pragma unroll
            for (int j = 0; j < 2; j++)
                wmma::load_matrix_sync(bf[j], &Bh[kk * LDB + wn + j * 16], LDB);
#pragma unroll
            for (int i = 0; i < 2; i++)
#pragma unroll
                for (int j = 0; j < 2; j++)
                    wmma::mma_sync(acc[i][j], af[i], bf[j], acc[i][j]);
        }
        __syncthreads();
    }

#pragma unroll
    for (int i = 0; i < 2; i++)
#pragma unroll
        for (int j = 0; j < 2; j++)
            wmma::store_matrix_sync(&Cs[(wm + i * 16) * LDC + wn + j * 16], acc[i][j],
                                    LDC, wmma::mem_row_major);
    __syncthreads();

    {
        int r = tid >> 1;
        int hh = tid & 1;
        int gr = row0 + r;
        int h = blockIdx.y * 2 + hh;
        const float* crow = &Cs[r * LDC + hh * 32];
        if (gr < NN) {
            float ps = 0.0f, pd = 0.0f;
            const float* avs = &a1s[h * HID];
            const float* avd = &a1d[h * HID];
            __half2 hbuf[16];
#pragma unroll
            for (int c = 0; c < 32; c += 2) {
                float v0 = crow[c], v1 = crow[c + 1];
                ps += v0 * avs[c] + v1 * avs[c + 1];
                pd += v0 * avd[c] + v1 * avd[c + 1];
                hbuf[c >> 1] = __float22half2_rn(make_float2(v0, v1));
            }
            g_as1[gr * HEADS + h] = ps;
            g_ad1[gr * HEADS + h] = pd;
            __half2* hp = (__half2*)&g_h1h[gr * HC + h * HID];
#pragma unroll
            for (int c = 0; c < 16; c += 4)
                *(uint4*)&hp[c] = *(uint4*)&hbuf[c];
        }
    }
}

// ---------------- GEMM2 (tensor core): g_h2h @ W2h -> g_g2/g_g2h + fused alpha2 ----------------
__global__ __launch_bounds__(256) void k_gemm2(const float* __restrict__ a2s,
                                               const float* __restrict__ a2d) {
    const int BM = 128, BN = 64, BK = 32;
    const int LDA = BK + 8;
    const int LDB = BN + 8;
    const int LDC = BN + 8;
    __shared__ __align__(16) __half Ah[BM * LDA];
    __shared__ __align__(16) __half Bh[BK * LDB];
    __shared__ __align__(16) float  Cs[BM * LDC];

    int tid = threadIdx.x;
    int wid = tid >> 5;
    int row0 = blockIdx.x * BM;
    int wm = (wid & 3) * 32;
    int wn = (wid >> 2) * 32;

    wmma::fragment<wmma::accumulator, 16, 16, 16, float> acc[2][2];
#pragma unroll
    for (int i = 0; i < 2; i++)
#pragma unroll
        for (int j = 0; j < 2; j++)
            wmma::fill_fragment(acc[i][j], 0.0f);

    for (int k0 = 0; k0 < HC; k0 += BK) {
#pragma unroll
        for (int q = 0; q < 2; q++) {
            int li = tid * 2 + q;
            int r = li >> 2;
            int c8 = li & 3;
            int gr = row0 + r;
            if (gr > NN - 1) gr = NN - 1;
            *(uint4*)&Ah[r * LDA + c8 * 8] = *(const uint4*)&g_h2h[gr * HC + k0 + c8 * 8];
        }
        {
            int r = tid >> 3;
            int c8 = tid & 7;
            *(uint4*)&Bh[r * LDB + c8 * 8] = *(const uint4*)&g_w2h[(k0 + r) * CLSP + c8 * 8];
        }
        __syncthreads();
#pragma unroll
        for (int kk = 0; kk < BK; kk += 16) {
            wmma::fragment<wmma::matrix_a, 16, 16, 16, __half, wmma::row_major> af[2];
            wmma::fragment<wmma::matrix_b, 16, 16, 16, __half, wmma::row_major> bf[2];
#pragma unroll
            for (int i = 0; i < 2; i++)
                wmma::load_matrix_sync(af[i], &Ah[(wm + i * 16) * LDA + kk], LDA);
#pragma unroll
            for (int j = 0; j < 2; j++)
                wmma::load_matrix_sync(bf[j], &Bh[kk * LDB + wn + j * 16], LDB);
#pragma unroll
            for (int i = 0; i < 2; i++)
#pragma unroll
                for (int j = 0; j < 2; j++)
                    wmma::mma_sync(acc[i][j], af[i], bf[j], acc[i][j]);
        }
        __syncthreads();
    }

#pragma unroll
    for (int i = 0; i < 2; i++)
#pragma unroll
        for (int j = 0; j < 2; j++)
            wmma::store_matrix_sync(&Cs[(wm + i * 16) * LDC + wn + j * 16], acc[i][j],
                                    LDC, wmma::mem_row_major);
    __syncthreads();

    {
        int r = tid >> 1;
        int part = tid & 1;
        int gr = row0 + r;
        const float* crow = &Cs[r * LDC + part * 20];
        if (gr < NN) {
            float ps = 0.0f, pd = 0.0f;
#pragma unroll
            for (int c = 0; c < 20; c++) {
                float v = crow[c];
                int col = part * 20 + c;
                ps += v * a2s[col];
                pd += v * a2d[col];
                g_g2[gr * CLS + col] = v;
            }
#pragma unroll
            for (int c = 0; c < 20; c += 2) {
                *(__half2*)&g_g2h[gr * CLS + part * 20 + c] =
                    __float22half2_rn(make_float2(crow[c], crow[c + 1]));
            }
            ps += __shfl_xor_sync(0xffffffffu, ps, 1);
            pd += __shfl_xor_sync(0xffffffffu, pd, 1);
            if (part == 0) {
                g_as2[gr] = ps;
                g_ad2[gr] = pd;
            }
        } else {
            __shfl_xor_sync(0xffffffffu, 0.0f, 1);
            __shfl_xor_sync(0xffffffffu, 0.0f, 1);
        }
    }
}

// ---------------- layer1: online softmax + fp16 gather + bias + ELU -> g_h2h ----------------
// 128 threads per dst node; warp wp covers heads 2wp, 2wp+1; unrolled 16-edge fast path.
__global__ __launch_bounds__(128) void k_agg1(const float* __restrict__ b1) {
    int n = blockIdx.x;
    int wp = threadIdx.x >> 5;          // 0..3
    int lane = threadIdx.x & 31;
    int hl = lane >> 4;                 // head within pair
    int h = wp * 2 + hl;
    int el = lane & 15;                 // edge slot within 16-edge chunk
    int beg = g_rowptr[n], end = g_rowptr[n + 1];
    float ad = g_ad1[n * HEADS + h];
    const __half2* __restrict__ h1h2 = (const __half2*)g_h1h;
    const int coff = wp * 32 + lane;    // half2 column within row

    float m = -INFINITY, ssum = 0.0f;
    float2 accA = make_float2(0.0f, 0.0f);
    float2 accB = make_float2(0.0f, 0.0f);

    int i0 = beg;
    // fast path: full 16-edge chunks, gather fully unrolled (MLP=16)
    for (; i0 + 16 <= end; i0 += 16) {
        int sl = g_esrc[i0 + el];
        float e = lrelu(g_as1[sl * HEADS + h] + ad);
        float cm = e;
#pragma unroll
        for (int o = 8; o; o >>= 1) cm = fmaxf(cm, __shfl_xor_sync(0xffffffffu, cm, o));
        float mn = fmaxf(m, cm);
        float sc = __expf(m - mn);
        accA.x *= sc; accA.y *= sc; accB.x *= sc; accB.y *= sc; ssum *= sc;
        m = mn;
        float w = __expf(e - mn);
        float ws = w;
#pragma unroll
        for (int o = 8; o; o >>= 1) ws += __shfl_xor_sync(0xffffffffu, ws, o);
        ssum += ws;
#pragma unroll
        for (int j = 0; j < 16; j += 2) {
            int   sA = __shfl_sync(0xffffffffu, sl, j);
            float wA = __shfl_sync(0xffffffffu, w, j + (hl << 4));
            int   sB = __shfl_sync(0xffffffffu, sl, j + 1);
            float wB = __shfl_sync(0xffffffffu, w, j + 1 + (hl << 4));
            float2 vA = __half22float2(h1h2[sA * (HC / 2) + coff]);
            float2 vB = __half22float2(h1h2[sB * (HC / 2) + coff]);
            accA.x += wA * vA.x; accA.y += wA * vA.y;
            accB.x += wB * vB.x; accB.y += wB * vB.y;
        }
    }
    // tail chunk
    if (i0 < end) {
        int i = i0 + el;
        int sl = 0;
        float e = -INFINITY;
        if (i < end) {
            sl = g_esrc[i];
            e = lrelu(g_as1[sl * HEADS + h] + ad);
        }
        float cm = e;
#pragma unroll
        for (int o = 8; o; o >>= 1) cm = fmaxf(cm, __shfl_xor_sync(0xffffffffu, cm, o));
        float mn = fmaxf(m, cm);
        float sc = __expf(m - mn);
        accA.x *= sc; accA.y *= sc; accB.x *= sc; accB.y *= sc; ssum *= sc;
        m = mn;
        float w = (i < end) ? __expf(e - mn) : 0.0f;
        float ws = w;
#pragma unroll
        for (int o = 8; o; o >>= 1) ws += __shfl_xor_sync(0xffffffffu, ws, o);
        ssum += ws;
        int lim = end - i0;
        for (int j = 0; j < lim; j++) {
            int   s2 = __shfl_sync(0xffffffffu, sl, j);
            float wj = __shfl_sync(0xffffffffu, w, j + (hl << 4));
            float2 v = __half22float2(h1h2[s2 * (HC / 2) + coff]);
            accA.x += wj * v.x;
            accA.y += wj * v.y;
        }
    }
    int c0 = wp * 64 + lane * 2;
    float inv_s = 1.0f / ssum;
    float o0 = (accA.x + accB.x) * inv_s + b1[c0];
    float o1 = (accA.y + accB.y) * inv_s + b1[c0 + 1];
    o0 = (o0 > 0.0f) ? o0 : (__expf(o0) - 1.0f);
    o1 = (o1 > 0.0f) ? o1 : (__expf(o1) - 1.0f);
    *(__half2*)&g_h2h[n * HC + c0] = __float22half2_rn(make_float2(o0, o1));
}

// ---------------- layer2: warp-per-node online softmax + fp16 gather + log_softmax ----------------
// 128 threads = 4 warps, one node per warp; shfl-only, no __syncthreads.
__global__ __launch_bounds__(128) void k_agg2(const float* __restrict__ b2,
                                              float* __restrict__ out) {
    int n = blockIdx.x * 4 + (threadIdx.x >> 5);
    if (n >= NN) return;
    int lane = threadIdx.x & 31;
    int beg = g_rowptr[n], end = g_rowptr[n + 1];
    float ad = g_ad2[n];
    const __half2* __restrict__ g2h2 = (const __half2*)g_g2h;

    float m = -INFINITY, ssum = 0.0f;
    float2 accA = make_float2(0.0f, 0.0f);
    float2 accB = make_float2(0.0f, 0.0f);

    int i0 = beg;
    for (; i0 + 32 <= end; i0 += 32) {
        int s = g_esrc[i0 + lane];
        float e = lrelu(g_as2[s] + ad);
        float cm = e;
#pragma unroll
        for (int o = 16; o; o >>= 1) cm = fmaxf(cm, __shfl_xor_sync(0xffffffffu, cm, o));
        float mn = fmaxf(m, cm);
        float sc = __expf(m - mn);
        accA.x *= sc; accA.y *= sc; accB.x *= sc; accB.y *= sc; ssum *= sc;
        m = mn;
        float w = __expf(e - mn);
        float ws = w;
#pragma unroll
        for (int o = 16; o; o >>= 1) ws += __shfl_xor_sync(0xffffffffu, ws, o);
        ssum += ws;
#pragma unroll
        for (int j = 0; j < 32; j += 2) {
            int   sA = __shfl_sync(0xffffffffu, s, j);
            float wA = __shfl_sync(0xffffffffu, w, j);
            int   sB = __shfl_sync(0xffffffffu, s, j + 1);
            float wB = __shfl_sync(0xffffffffu, w, j + 1);
            if (lane < CLS / 2) {
                float2 vA = __half22float2(g2h2[sA * (CLS / 2) + lane]);
                float2 vB = __half22float2(g2h2[sB * (CLS / 2) + lane]);
                accA.x += wA * vA.x; accA.y += wA * vA.y;
                accB.x += wB * vB.x; accB.y += wB * vB.y;
            }
        }
    }
    if (i0 < end) {
        int i = i0 + lane;
        int s = 0;
        float e = -INFINITY;
        if (i < end) {
            s = g_esrc[i];
            e = lrelu(g_as2[s] + ad);
        }
        float cm = e;
#pragma unroll
        for (int o = 16; o; o >>= 1) cm = fmaxf(cm, __shfl_xor_sync(0xffffffffu, cm, o));
        float mn = fmaxf(m, cm);
        float sc = __expf(m - mn);
        accA.x *= sc; accA.y *= sc; accB.x *= sc; accB.y *= sc; ssum *= sc;
        m = mn;
        float w = (i < end) ? __expf(e - mn) : 0.0f;
        float ws = w;
#pragma unroll
        for (int o = 16; o; o >>= 1) ws += __shfl_xor_sync(0xffffffffu, ws, o);
        ssum += ws;
        int lim = end - i0;
        for (int j = 0; j < lim; j++) {
            int   s2 = __shfl_sync(0xffffffffu, s, j);
            float wj = __shfl_sync(0xffffffffu, w, j);
            if (lane < CLS / 2) {
                float2 v = __half22float2(g2h2[s2 * (CLS / 2) + lane]);
                accA.x += wj * v.x;
                accA.y += wj * v.y;
            }
        }
    }

    float inv_s = 1.0f / ssum;
    float o0 = -INFINITY, o1 = -INFINITY;
    if (lane < CLS / 2) {
        o0 = (accA.x + accB.x) * inv_s + b2[lane * 2];
        o1 = (accA.y + accB.y) * inv_s + b2[lane * 2 + 1];
    }
    // warp log-softmax over 40 values (20 lanes x 2)
    float lm = fmaxf(o0, o1);
#pragma unroll
    for (int o = 16; o; o >>= 1) lm = fmaxf(lm, __shfl_xor_sync(0xffffffffu, lm, o));
    float le = (lane < CLS / 2) ? (__expf(o0 - lm) + __expf(o1 - lm)) : 0.0f;
#pragma unroll
    for (int o = 16; o; o >>= 1) le += __shfl_xor_sync(0xffffffffu, le, o);
    float lse = logf(le);
    if (lane < CLS / 2) {
        out[n * CLS + lane * 2]     = o0 - lm - lse;
        out[n * CLS + lane * 2 + 1] = o1 - lm - lse;
    }
}

// ---------------- launch ----------------
extern "C" void kernel_launch(void* const* d_in, const int* in_sizes, int n_in,
                              void* d_out, int out_size) {
    const float* x   = (const float*)d_in[0];
    const int*   ei  = (const int*)d_in[1];      // edge_index is int32 (JAX x64 disabled)
    const float* W1  = (const float*)d_in[2];
    const float* a1s = (const float*)d_in[3];
    const float* a1d = (const float*)d_in[4];
    const float* b1  = (const float*)d_in[5];
    const float* W2  = (const float*)d_in[6];
    const float* a2s = (const float*)d_in[7];
    const float* a2d = (const float*)d_in[8];
    const float* b2  = (const float*)d_in[9];
    float*       out = (float*)d_out;

    // prep: fp16 conversion + CSR build (multi-block scan)
    k_init<<<(NN + 255) / 256, 256>>>();
    k_cvt<<<((NN * FEAT + FEAT * HC + HC * CLSP) / 2 + 255) / 256, 256>>>(x, W1, W2);
    k_count<<<(TOT / 4 + 255) / 256, 256>>>(ei);
    k_bsum<<<NB, 256>>>();
    k_bscan<<<1, 128>>>();
    k_writeptr<<<NB, 256>>>();
    k_scatter<<<(TOT + 255) / 256, 256>>>(ei);

    // layer 1
    k_gemm1<<<dim3((NN + 127) / 128, HC / 64), 256>>>(a1s, a1d);
    k_agg1<<<NN, 128>>>(b1);

    // layer 2
    k_gemm2<<<(NN + 127) / 128, 256>>>(a2s, a2d);
    k_agg2<<<(NN + 3) / 4, 128>>>(b2, out);
}

// round 13
// speedup vs baseline: 1.3099x; 1.3099x over previous
#include <cuda_runtime.h>
#include <cuda_fp16.h>
#include <mma.h>
#include <math.h>

using namespace nvcuda;

#define NN 20000
#define FEAT 128
#define HID 32
#define HEADS 8
#define HC 256          // HEADS*HID
#define CLS 40
#define CLSP 64         // padded cols for tensor GEMM2
#define E_IN 640000
#define TOT (E_IN + NN)
#define NEG 0.2f
#define NB ((NN + 255) / 256)   // 79 scan blocks

// ---------------- scratch (device globals; no allocation allowed) ----------------
__device__ __half g_xh[NN * FEAT];     // x in fp16
__device__ __half g_w1h[FEAT * HC];    // W1 in fp16
__device__ __half g_w2h[HC * CLSP];    // W2 in fp16, zero-padded to 64 cols
__device__ __half g_h1h[NN * HC];      // layer1 linear output (fp16, for gather)
__device__ __half g_h2h[NN * HC];      // layer1 GAT output after ELU (fp16)
__device__ float  g_as1[NN * HEADS];
__device__ float  g_ad1[NN * HEADS];
__device__ float  g_g2[NN * CLS];      // layer2 linear output (fp32)
__device__ __half g_g2h[NN * CLS];     // layer2 linear output (fp16, for gather)
__device__ float  g_as2[NN];
__device__ float  g_ad2[NN];
__device__ int    g_rowptr[NN + 1];
__device__ int    g_cnt[NN];
__device__ int    g_cur[NN];
__device__ int    g_bsum[128];
__device__ int    g_boff[128];
__device__ int    g_esrc[TOT];         // src node per CSR slot (sorted by dst)

// ---------------- helpers (edge_index is INT32; loads always in-bounds) ----------------
__device__ __forceinline__ int edge_src(const int* ei, int e) {
    int idx = (e < E_IN) ? e : 0;
    int v = ei[idx];
    return (e < E_IN) ? v : (e - E_IN);
}
__device__ __forceinline__ int edge_dst(const int* ei, int e) {
    int idx = (e < E_IN) ? (E_IN + e) : 0;
    int v = ei[idx];
    return (e < E_IN) ? v : (e - E_IN);
}
__device__ __forceinline__ float lrelu(float v) { return v > 0.0f ? v : NEG * v; }

// ---------------- fp16 conversion + cnt zeroing ----------------
__global__ void k_cvt(const float* __restrict__ x, const float* __restrict__ W1,
                      const float* __restrict__ W2) {
    int t = blockIdx.x * blockDim.x + threadIdx.x;
    const int NX = NN * FEAT / 2;           // half2 units of x
    const int NW = FEAT * HC / 2;           // half2 units of W1
    const int NW2 = HC * CLSP / 2;          // half2 units of padded W2
    if (t < NN) g_cnt[t] = 0;
    if (t < NX) {
        float2 v = *(const float2*)&x[t * 2];
        *(__half2*)&g_xh[t * 2] = __float22half2_rn(v);
    } else if (t < NX + NW) {
        int u = t - NX;
        float2 v = *(const float2*)&W1[u * 2];
        *(__half2*)&g_w1h[u * 2] = __float22half2_rn(v);
    } else if (t < NX + NW + NW2) {
        int u = t - NX - NW;
        int row = u / (CLSP / 2);
        int cp = (u % (CLSP / 2)) * 2;
        float v0 = (cp < CLS) ? W2[row * CLS + cp] : 0.0f;
        float v1 = (cp + 1 < CLS) ? W2[row * CLS + cp + 1] : 0.0f;
        *(__half2*)&g_w2h[u * 2] = __float22half2_rn(make_float2(v0, v1));
    }
}

// ---------------- CSR build ----------------
__global__ void k_count(const int* __restrict__ ei) {
    int t = blockIdx.x * blockDim.x + threadIdx.x;
    int e0 = t * 4;
    if (e0 >= TOT) return;
    if (e0 + 3 < E_IN) {
        int4 d4 = *(const int4*)&ei[E_IN + e0];
        atomicAdd(&g_cnt[d4.x], 1);
        atomicAdd(&g_cnt[d4.y], 1);
        atomicAdd(&g_cnt[d4.z], 1);
        atomicAdd(&g_cnt[d4.w], 1);
    } else {
        for (int k = 0; k < 4 && e0 + k < TOT; k++)
            atomicAdd(&g_cnt[edge_dst(ei, e0 + k)], 1);
    }
}

// Multi-block scan, phase 1: per-block sums of 256 counts
__global__ void k_bsum() {
    __shared__ int sm[256];
    int t = threadIdx.x;
    int i = blockIdx.x * 256 + t;
    int v = (i < NN) ? g_cnt[i] : 0;
    sm[t] = v;
    __syncthreads();
    for (int off = 128; off; off >>= 1) {
        if (t < off) sm[t] += sm[t + off];
        __syncthreads();
    }
    if (t == 0) g_bsum[blockIdx.x] = sm[0];
}

// phase 2: scan NB block sums (single block of 128)
__global__ void k_bscan() {
    __shared__ int sm[128];
    int t = threadIdx.x;
    int v = (t < NB) ? g_bsum[t] : 0;
    sm[t] = v;
    __syncthreads();
    for (int off = 1; off < 128; off <<= 1) {
        int idx = (t >= off) ? (t - off) : t;
        int add = sm[idx];
        if (t < off) add = 0;
        __syncthreads();
        sm[t] += add;
        __syncthreads();
    }
    if (t < NB) g_boff[t] = sm[t] - v;     // exclusive
    if (t == 127) g_rowptr[NN] = sm[127];
}

// phase 3: per-block exclusive scan + global offset -> rowptr/cur
__global__ void k_writeptr() {
    __shared__ int sm[256];
    int t = threadIdx.x;
    int i = blockIdx.x * 256 + t;
    int v = (i < NN) ? g_cnt[i] : 0;
    sm[t] = v;
    __syncthreads();
    for (int off = 1; off < 256; off <<= 1) {
        int idx = (t >= off) ? (t - off) : t;
        int add = sm[idx];
        if (t < off) add = 0;
        __syncthreads();
        sm[t] += add;
        __syncthreads();
    }
    if (i < NN) {
        int excl = sm[t] - v + g_boff[blockIdx.x];
        g_rowptr[i] = excl;
        g_cur[i] = excl;
    }
}

__global__ void k_scatter(const int* __restrict__ ei) {
    int t = blockIdx.x * blockDim.x + threadIdx.x;
    if (t >= TOT) return;
    int d = edge_dst(ei, t);
    int s = edge_src(ei, t);
    int pos = atomicAdd(&g_cur[d], 1);
    g_esrc[pos] = s;
}

// ---------------- GEMM1 (tensor core): xh @ W1h -> g_h1h + fused alpha1 ----------------
__global__ __launch_bounds__(256) void k_gemm1(const float* __restrict__ a1s,
                                               const float* __restrict__ a1d) {
    const int BM = 128, BN = 64, BK = 32;
    const int LDA = BK + 8;
    const int LDB = BN + 8;
    const int LDC = BN + 8;
    __shared__ __align__(16) __half Ah[BM * LDA];
    __shared__ __align__(16) __half Bh[BK * LDB];
    __shared__ __align__(16) float  Cs[BM * LDC];

    int tid = threadIdx.x;
    int wid = tid >> 5;
    int row0 = blockIdx.x * BM;
    int col0 = blockIdx.y * BN;
    int wm = (wid & 3) * 32;
    int wn = (wid >> 2) * 32;

    wmma::fragment<wmma::accumulator, 16, 16, 16, float> acc[2][2];
#pragma unroll
    for (int i = 0; i < 2; i++)
#pragma unroll
        for (int j = 0; j < 2; j++)
            wmma::fill_fragment(acc[i][j], 0.0f);

    for (int k0 = 0; k0 < FEAT; k0 += BK) {
#pragma unroll
        for (int q = 0; q < 2; q++) {
            int li = tid * 2 + q;
            int r = li >> 2;
            int c8 = li & 3;
            int gr = row0 + r;
            if (gr > NN - 1) gr = NN - 1;
            *(uint4*)&Ah[r * LDA + c8 * 8] = *(const uint4*)&g_xh[gr * FEAT + k0 + c8 * 8];
        }
        {
            int r = tid >> 3;
            int c8 = tid & 7;
            *(uint4*)&Bh[r * LDB + c8 * 8] = *(const uint4*)&g_w1h[(k0 + r) * HC + col0 + c8 * 8];
        }
        __syncthreads();
#pragma unroll
        for (int kk = 0; kk < BK; kk += 16) {
            wmma::fragment<wmma::matrix_a, 16, 16, 16, __half, wmma::row_major> af[2];
            wmma::fragment<wmma::matrix_b, 16, 16, 16, __half, wmma::row_major> bf[2];
#pragma unroll
            for (int i = 0; i < 2; i++)
                wmma::load_matrix_sync(af[i], &Ah[(wm + i * 16) * LDA + kk], LDA);
#pragma unroll
            for (int j = 0; j < 2; j++)
                wmma::load_matrix_sync(bf[j], &Bh[kk * LDB + wn + j * 16], LDB);
#pragma unroll
            for (int i = 0; i < 2; i++)
#pragma unroll
                for (int j = 0; j < 2; j++)
                    wmma::mma_sync(acc[i][j], af[i], bf[j], acc[i][j]);
        }
        __syncthreads();
    }

#pragma unroll
    for (int i = 0; i < 2; i++)
#pragma unroll
        for (int j = 0; j < 2; j++)
            wmma::store_matrix_sync(&Cs[(wm + i * 16) * LDC + wn + j * 16], acc[i][j],
                                    LDC, wmma::mem_row_major);
    __syncthreads();

    {
        int r = tid >> 1;
        int hh = tid & 1;
        int gr = row0 + r;
        int h = blockIdx.y * 2 + hh;
        const float* crow = &Cs[r * LDC + hh * 32];
        if (gr < NN) {
            float ps = 0.0f, pd = 0.0f;
            const float* avs = &a1s[h * HID];
            const float* avd = &a1d[h * HID];
            __half2 hbuf[16];
#pragma unroll
            for (int c = 0; c < 32; c += 2) {
                float v0 = crow[c], v1 = crow[c + 1];
                ps += v0 * avs[c] + v1 * avs[c + 1];
                pd += v0 * avd[c] + v1 * avd[c + 1];
                hbuf[c >> 1] = __float22half2_rn(make_float2(v0, v1));
            }
            g_as1[gr * HEADS + h] = ps;
            g_ad1[gr * HEADS + h] = pd;
            __half2* hp = (__half2*)&g_h1h[gr * HC + h * HID];
#pragma unroll
            for (int c = 0; c < 16; c += 4)
                *(uint4*)&hp[c] = *(uint4*)&hbuf[c];
        }
    }
}

// ---------------- GEMM2 (tensor core): g_h2h @ W2h -> g_g2/g_g2h + fused alpha2 ----------------
__global__ __launch_bounds__(256) void k_gemm2(const float* __restrict__ a2s,
                                               const float* __restrict__ a2d) {
    const int BM = 128, BN = 64, BK = 32;
    const int LDA = BK + 8;
    const int LDB = BN + 8;
    const int LDC = BN + 8;
    __shared__ __align__(16) __half Ah[BM * LDA];
    __shared__ __align__(16) __half Bh[BK * LDB];
    __shared__ __align__(16) float  Cs[BM * LDC];

    int tid = threadIdx.x;
    int wid = tid >> 5;
    int row0 = blockIdx.x * BM;
    int wm = (wid & 3) * 32;
    int wn = (wid >> 2) * 32;

    wmma::fragment<wmma::accumulator, 16, 16, 16, float> acc[2][2];
#pragma unroll
    for (int i = 0; i < 2; i++)
#pragma unroll
        for (int j = 0; j < 2; j++)
            wmma::fill_fragment(acc[i][j], 0.0f);

    for (int k0 = 0; k0 < HC; k0 += BK) {
#pragma unroll
        for (int q = 0; q < 2; q++) {
            int li = tid * 2 + q;
            int r = li >> 2;
            int c8 = li & 3;
            int gr = row0 + r;
            if (gr > NN - 1) gr = NN - 1;
            *(uint4*)&Ah[r * LDA + c8 * 8] = *(const uint4*)&g_h2h[gr * HC + k0 + c8 * 8];
        }
        {
            int r = tid >> 3;
            int c8 = tid & 7;
            *(uint4*)&Bh[r * LDB + c8 * 8] = *(const uint4*)&g_w2h[(k0 + r) * CLSP + c8 * 8];
        }
        __syncthreads();
#pragma unroll
        for (int kk = 0; kk < BK; kk += 16) {
            wmma::fragment<wmma::matrix_a, 16, 16, 16, __half, wmma::row_major> af[2];
            wmma::fragment<wmma::matrix_b, 16, 16, 16, __half, wmma::row_major> bf[2];
#pragma unroll
            for (int i = 0; i < 2; i++)
                wmma::load_matrix_sync(af[i], &Ah[(wm + i * 16) * LDA + kk], LDA);
#pragma unroll
            for (int j = 0; j < 2; j++)
                wmma::load_matrix_sync(bf[j], &Bh[kk * LDB + wn + j * 16], LDB);
#pragma unroll
            for (int i = 0; i < 2; i++)
#pragma unroll
                for (int j = 0; j < 2; j++)
                    wmma::mma_sync(acc[i][j], af[i], bf[j], acc[i][j]);
        }
        __syncthreads();
    }

#pragma unroll
    for (int i = 0; i < 2; i++)
#pragma unroll
        for (int j = 0; j < 2; j++)
            wmma::store_matrix_sync(&Cs[(wm + i * 16) * LDC + wn + j * 16], acc[i][j],
                                    LDC, wmma::mem_row_major);
    __syncthreads();

    {
        int r = tid >> 1;
        int part = tid & 1;
        int gr = row0 + r;
        const float* crow = &Cs[r * LDC + part * 20];
        if (gr < NN) {
            float ps = 0.0f, pd = 0.0f;
#pragma unroll
            for (int c = 0; c < 20; c++) {
                float v = crow[c];
                int col = part * 20 + c;
                ps += v * a2s[col];
                pd += v * a2d[col];
                g_g2[gr * CLS + col] = v;
            }
#pragma unroll
            for (int c = 0; c < 20; c += 2) {
                *(__half2*)&g_g2h[gr * CLS + part * 20 + c] =
                    __float22half2_rn(make_float2(crow[c], crow[c + 1]));
            }
            ps += __shfl_xor_sync(0xffffffffu, ps, 1);
            pd += __shfl_xor_sync(0xffffffffu, pd, 1);
            if (part == 0) {
                g_as2[gr] = ps;
                g_ad2[gr] = pd;
            }
        } else {
            __shfl_xor_sync(0xffffffffu, 0.0f, 1);
            __shfl_xor_sync(0xffffffffu, 0.0f, 1);
        }
    }
}

// ---------------- layer1: online softmax + fp16 gather + bias + ELU -> g_h2h ----------------
// 128 threads per dst node; warp wp covers heads 2wp, 2wp+1 (64 channels = 32 half2).
__global__ __launch_bounds__(128) void k_agg1(const float* __restrict__ b1) {
    int n = blockIdx.x;
    int wp = threadIdx.x >> 5;          // 0..3
    int lane = threadIdx.x & 31;
    int hl = lane >> 4;                 // head within pair
    int h = wp * 2 + hl;
    int el = lane & 15;                 // edge slot within 16-edge chunk
    int beg = g_rowptr[n], end = g_rowptr[n + 1];
    float ad = g_ad1[n * HEADS + h];
    const __half2* __restrict__ h1h2 = (const __half2*)g_h1h;

    float m = -INFINITY, ssum = 0.0f;
    float2 acc = make_float2(0.0f, 0.0f);
    for (int i0 = beg; i0 < end; i0 += 16) {
        int i = i0 + el;
        int sl = 0;
        float e = -INFINITY;
        if (i < end) {
            sl = g_esrc[i];
            e = lrelu(g_as1[sl * HEADS + h] + ad);
        }
        float cm = e;
#pragma unroll
        for (int o = 8; o; o >>= 1) cm = fmaxf(cm, __shfl_xor_sync(0xffffffffu, cm, o));
        float mn = fmaxf(m, cm);
        float sc = __expf(m - mn);
        acc.x *= sc; acc.y *= sc; ssum *= sc;
        m = mn;
        float w = (i < end) ? __expf(e - mn) : 0.0f;
        float ws = w;
#pragma unroll
        for (int o = 8; o; o >>= 1) ws += __shfl_xor_sync(0xffffffffu, ws, o);
        ssum += ws;
        int lim = min(16, end - i0);
#pragma unroll 4
        for (int j = 0; j < lim; j++) {
            int   s2 = __shfl_sync(0xffffffffu, sl, j);
            float wj = __shfl_sync(0xffffffffu, w, j + (hl << 4));
            float2 v = __half22float2(h1h2[s2 * (HC / 2) + wp * 32 + lane]);
            acc.x += wj * v.x;
            acc.y += wj * v.y;
        }
    }
    int c0 = wp * 64 + lane * 2;
    float inv_s = 1.0f / ssum;
    float o0 = acc.x * inv_s + b1[c0];
    float o1 = acc.y * inv_s + b1[c0 + 1];
    o0 = (o0 > 0.0f) ? o0 : (__expf(o0) - 1.0f);
    o1 = (o1 > 0.0f) ? o1 : (__expf(o1) - 1.0f);
    *(__half2*)&g_h2h[n * HC + c0] = __float22half2_rn(make_float2(o0, o1));
}

// ---------------- layer2: online softmax + fp16 gather + bias + log_softmax ----------------
__global__ void k_agg2(const float* __restrict__ b2, float* __restrict__ out) {
    int n = blockIdx.x;
    int t = threadIdx.x;
    __shared__ float red[64];
    __shared__ int   s_src[64];
    __shared__ float s_w[64];
    __shared__ float o40[CLS];
    int beg = g_rowptr[n], end = g_rowptr[n + 1];
    float ad = g_ad2[n];
    const __half2* __restrict__ g2h2 = (const __half2*)g_g2h;

    float m = -INFINITY, ssum = 0.0f;
    float2 acc = make_float2(0.0f, 0.0f);
    for (int i0 = beg; i0 < end; i0 += 64) {
        int i = i0 + t;
        int s = 0;
        float e = -INFINITY;
        if (i < end) {
            s = g_esrc[i];
            e = lrelu(g_as2[s] + ad);
        }
        red[t] = e; __syncthreads();
        for (int off = 32; off; off >>= 1) { if (t < off) red[t] = fmaxf(red[t], red[t + off]); __syncthreads(); }
        float mn = fmaxf(m, red[0]);
        __syncthreads();
        float scale = __expf(m - mn);
        acc.x *= scale; acc.y *= scale;
        ssum *= scale;
        m = mn;
        float w = (i < end) ? __expf(e - mn) : 0.0f;
        s_src[t] = s;
        s_w[t] = w;
        red[t] = w; __syncthreads();
        for (int off = 32; off; off >>= 1) { if (t < off) red[t] += red[t + off]; __syncthreads(); }
        ssum += red[0];
        __syncthreads();
        int lim = min(64, end - i0);
        if (t < CLS / 2) {
#pragma unroll 4
            for (int j = 0; j < lim; j++) {
                float2 v = __half22float2(g2h2[s_src[j] * (CLS / 2) + t]);
                acc.x += s_w[j] * v.x;
                acc.y += s_w[j] * v.y;
            }
        }
        __syncthreads();
    }

    if (t < CLS / 2) {
        float inv_s = 1.0f / ssum;
        o40[t * 2]     = acc.x * inv_s + b2[t * 2];
        o40[t * 2 + 1] = acc.y * inv_s + b2[t * 2 + 1];
    }
    __syncthreads();
    float o = (t < CLS) ? o40[t] : -INFINITY;
    red[t] = o; __syncthreads();
    for (int off = 32; off; off >>= 1) { if (t < off) red[t] = fmaxf(red[t], red[t + off]); __syncthreads(); }
    float mx = red[0]; __syncthreads();
    red[t] = (t < CLS) ? __expf(o - mx) : 0.0f;
    __syncthreads();
    for (int off = 32; off; off >>= 1) { if (t < off) red[t] += red[t + off]; __syncthreads(); }
    if (t < CLS) out[n * CLS + t] = o - mx - logf(red[0]);
}

// ---------------- launch ----------------
extern "C" void kernel_launch(void* const* d_in, const int* in_sizes, int n_in,
                              void* d_out, int out_size) {
    const float* x   = (const float*)d_in[0];
    const int*   ei  = (const int*)d_in[1];      // edge_index is int32 (JAX x64 disabled)
    const float* W1  = (const float*)d_in[2];
    const float* a1s = (const float*)d_in[3];
    const float* a1d = (const float*)d_in[4];
    const float* b1  = (const float*)d_in[5];
    const float* W2  = (const float*)d_in[6];
    const float* a2s = (const float*)d_in[7];
    const float* a2d = (const float*)d_in[8];
    const float* b2  = (const float*)d_in[9];
    float*       out = (float*)d_out;

    // prep: fp16 conversion (+cnt zeroing) + CSR build (multi-block scan)
    k_cvt<<<((NN * FEAT + FEAT * HC + HC * CLSP) / 2 + 255) / 256, 256>>>(x, W1, W2);
    k_count<<<(TOT / 4 + 255) / 256, 256>>>(ei);
    k_bsum<<<NB, 256>>>();
    k_bscan<<<1, 128>>>();
    k_writeptr<<<NB, 256>>>();
    k_scatter<<<(TOT + 255) / 256, 256>>>(ei);

    // layer 1
    k_gemm1<<<dim3((NN + 127) / 128, HC / 64), 256>>>(a1s, a1d);
    k_agg1<<<NN, 128>>>(b1);

    // layer 2
    k_gemm2<<<(NN + 127) / 128, 256>>>(a2s, a2d);
    k_agg2<<<NN, 64>>>(b2, out);
}

// round 14
// speedup vs baseline: 1.5421x; 1.1772x over previous
#include <cuda_runtime.h>
#include <cuda_fp16.h>
#include <mma.h>
#include <math.h>

using namespace nvcuda;

#define NN 20000
#define FEAT 128
#define HID 32
#define HEADS 8
#define HC 256          // HEADS*HID
#define CLS 40
#define CLSP 64         // padded cols for tensor GEMM2
#define E_IN 640000
#define TOT (E_IN + NN)
#define NEG 0.2f
#define NB ((NN + 255) / 256)   // 79 scan blocks

// ---------------- scratch (device globals; no allocation allowed) ----------------
__device__ __half g_xh[NN * FEAT];     // x in fp16
__device__ __half g_w1h[FEAT * HC];    // W1 in fp16
__device__ __half g_w2h[HC * CLSP];    // W2 in fp16, zero-padded to 64 cols
__device__ __half g_h1h[NN * HC];      // layer1 linear output (fp16, for gather)
__device__ __half g_h2h[NN * HC];      // layer1 GAT output after ELU (fp16)
__device__ float  g_as1[NN * HEADS];
__device__ float  g_ad1[NN * HEADS];
__device__ __half g_g2h[NN * CLS];     // layer2 linear output (fp16, for gather)
__device__ float  g_as2[NN];
__device__ float  g_ad2[NN];
__device__ int    g_rowptr[NN + 1];
__device__ int    g_cnt[NN];
__device__ int    g_cur[NN];
__device__ int    g_bsum[128];
__device__ int    g_boff[128];
__device__ int    g_esrc[TOT];         // src node per CSR slot (sorted by dst)

// ---------------- helpers (edge_index is INT32; loads always in-bounds) ----------------
__device__ __forceinline__ int edge_src(const int* ei, int e) {
    int idx = (e < E_IN) ? e : 0;
    int v = ei[idx];
    return (e < E_IN) ? v : (e - E_IN);
}
__device__ __forceinline__ int edge_dst(const int* ei, int e) {
    int idx = (e < E_IN) ? (E_IN + e) : 0;
    int v = ei[idx];
    return (e < E_IN) ? v : (e - E_IN);
}
__device__ __forceinline__ float lrelu(float v) { return v > 0.0f ? v : NEG * v; }

// ---------------- init + fp16 conversion ----------------
__global__ void k_init() {
    int t = blockIdx.x * blockDim.x + threadIdx.x;
    if (t < NN) g_cnt[t] = 0;
}

__global__ void k_cvt(const float* __restrict__ x, const float* __restrict__ W1,
                      const float* __restrict__ W2) {
    int t = blockIdx.x * blockDim.x + threadIdx.x;
    const int NX = NN * FEAT / 2;           // half2 units of x
    const int NW = FEAT * HC / 2;           // half2 units of W1
    const int NW2 = HC * CLSP / 2;          // half2 units of padded W2
    if (t < NX) {
        float2 v = *(const float2*)&x[t * 2];
        *(__half2*)&g_xh[t * 2] = __float22half2_rn(v);
    } else if (t < NX + NW) {
        int u = t - NX;
        float2 v = *(const float2*)&W1[u * 2];
        *(__half2*)&g_w1h[u * 2] = __float22half2_rn(v);
    } else if (t < NX + NW + NW2) {
        int u = t - NX - NW;
        int row = u / (CLSP / 2);
        int cp = (u % (CLSP / 2)) * 2;
        float v0 = (cp < CLS) ? W2[row * CLS + cp] : 0.0f;
        float v1 = (cp + 1 < CLS) ? W2[row * CLS + cp + 1] : 0.0f;
        *(__half2*)&g_w2h[u * 2] = __float22half2_rn(make_float2(v0, v1));
    }
}

// ---------------- CSR build ----------------
__global__ void k_count(const int* __restrict__ ei) {
    int t = blockIdx.x * blockDim.x + threadIdx.x;
    int e0 = t * 4;
    if (e0 >= TOT) return;
    if (e0 + 3 < E_IN) {
        int4 d4 = *(const int4*)&ei[E_IN + e0];
        atomicAdd(&g_cnt[d4.x], 1);
        atomicAdd(&g_cnt[d4.y], 1);
        atomicAdd(&g_cnt[d4.z], 1);
        atomicAdd(&g_cnt[d4.w], 1);
    } else {
        for (int k = 0; k < 4 && e0 + k < TOT; k++)
            atomicAdd(&g_cnt[edge_dst(ei, e0 + k)], 1);
    }
}

// Multi-block scan, phase 1: per-block sums of 256 counts
__global__ void k_bsum() {
    __shared__ int sm[256];
    int t = threadIdx.x;
    int i = blockIdx.x * 256 + t;
    int v = (i < NN) ? g_cnt[i] : 0;
    sm[t] = v;
    __syncthreads();
    for (int off = 128; off; off >>= 1) {
        if (t < off) sm[t] += sm[t + off];
        __syncthreads();
    }
    if (t == 0) g_bsum[blockIdx.x] = sm[0];
}

// phase 2: scan NB block sums (single block of 128)
__global__ void k_bscan() {
    __shared__ int sm[128];
    int t = threadIdx.x;
    int v = (t < NB) ? g_bsum[t] : 0;
    sm[t] = v;
    __syncthreads();
    for (int off = 1; off < 128; off <<= 1) {
        int idx = (t >= off) ? (t - off) : t;
        int add = sm[idx];
        if (t < off) add = 0;
        __syncthreads();
        sm[t] += add;
        __syncthreads();
    }
    if (t < NB) g_boff[t] = sm[t] - v;     // exclusive
    if (t == 127) g_rowptr[NN] = sm[127];
}

// phase 3: per-block exclusive scan + global offset -> rowptr/cur
__global__ void k_writeptr() {
    __shared__ int sm[256];
    int t = threadIdx.x;
    int i = blockIdx.x * 256 + t;
    int v = (i < NN) ? g_cnt[i] : 0;
    sm[t] = v;
    __syncthreads();
    for (int off = 1; off < 256; off <<= 1) {
        int idx = (t >= off) ? (t - off) : t;
        int add = sm[idx];
        if (t < off) add = 0;
        __syncthreads();
        sm[t] += add;
        __syncthreads();
    }
    if (i < NN) {
        int excl = sm[t] - v + g_boff[blockIdx.x];
        g_rowptr[i] = excl;
        g_cur[i] = excl;
    }
}

__global__ void k_scatter(const int* __restrict__ ei) {
    int t = blockIdx.x * blockDim.x + threadIdx.x;
    if (t >= TOT) return;
    int d = edge_dst(ei, t);
    int s = edge_src(ei, t);
    int pos = atomicAdd(&g_cur[d], 1);
    g_esrc[pos] = s;
}

// ---------------- GEMM1 (tensor core): xh @ W1h -> g_h1h + fused alpha1 ----------------
__global__ __launch_bounds__(256) void k_gemm1(const float* __restrict__ a1s,
                                               const float* __restrict__ a1d) {
    const int BM = 128, BN = 64, BK = 32;
    const int LDA = BK + 8;
    const int LDB = BN + 8;
    const int LDC = BN + 8;
    __shared__ __align__(16) __half Ah[BM * LDA];
    __shared__ __align__(16) __half Bh[BK * LDB];
    __shared__ __align__(16) float  Cs[BM * LDC];

    int tid = threadIdx.x;
    int wid = tid >> 5;
    int row0 = blockIdx.x * BM;
    int col0 = blockIdx.y * BN;
    int wm = (wid & 3) * 32;
    int wn = (wid >> 2) * 32;

    wmma::fragment<wmma::accumulator, 16, 16, 16, float> acc[2][2];
#pragma unroll
    for (int i = 0; i < 2; i++)
#pragma unroll
        for (int j = 0; j < 2; j++)
            wmma::fill_fragment(acc[i][j], 0.0f);

    for (int k0 = 0; k0 < FEAT; k0 += BK) {
#pragma unroll
        for (int q = 0; q < 2; q++) {
            int li = tid * 2 + q;
            int r = li >> 2;
            int c8 = li & 3;
            int gr = row0 + r;
            if (gr > NN - 1) gr = NN - 1;
            *(uint4*)&Ah[r * LDA + c8 * 8] = *(const uint4*)&g_xh[gr * FEAT + k0 + c8 * 8];
        }
        {
            int r = tid >> 3;
            int c8 = tid & 7;
            *(uint4*)&Bh[r * LDB + c8 * 8] = *(const uint4*)&g_w1h[(k0 + r) * HC + col0 + c8 * 8];
        }
        __syncthreads();
#pragma unroll
        for (int kk = 0; kk < BK; kk += 16) {
            wmma::fragment<wmma::matrix_a, 16, 16, 16, __half, wmma::row_major> af[2];
            wmma::fragment<wmma::matrix_b, 16, 16, 16, __half, wmma::row_major> bf[2];
#pragma unroll
            for (int i = 0; i < 2; i++)
                wmma::load_matrix_sync(af[i], &Ah[(wm + i * 16) * LDA + kk], LDA);
#pragma unroll
            for (int j = 0; j < 2; j++)
                wmma::load_matrix_sync(bf[j], &Bh[kk * LDB + wn + j * 16], LDB);
#pragma unroll
            for (int i = 0; i < 2; i++)
#pragma unroll
                for (int j = 0; j < 2; j++)
                    wmma::mma_sync(acc[i][j], af[i], bf[j], acc[i][j]);
        }
        __syncthreads();
    }

#pragma unroll
    for (int i = 0; i < 2; i++)
#pragma unroll
        for (int j = 0; j < 2; j++)
            wmma::store_matrix_sync(&Cs[(wm + i * 16) * LDC + wn + j * 16], acc[i][j],
                                    LDC, wmma::mem_row_major);
    __syncthreads();

    {
        int r = tid >> 1;
        int hh = tid & 1;
        int gr = row0 + r;
        int h = blockIdx.y * 2 + hh;
        const float* crow = &Cs[r * LDC + hh * 32];
        if (gr < NN) {
            float ps = 0.0f, pd = 0.0f;
            const float* avs = &a1s[h * HID];
            const float* avd = &a1d[h * HID];
            __half2 hbuf[16];
#pragma unroll
            for (int c = 0; c < 32; c += 2) {
                float v0 = crow[c], v1 = crow[c + 1];
                ps += v0 * avs[c] + v1 * avs[c + 1];
                pd += v0 * avd[c] + v1 * avd[c + 1];
                hbuf[c >> 1] = __float22half2_rn(make_float2(v0, v1));
            }
            g_as1[gr * HEADS + h] = ps;
            g_ad1[gr * HEADS + h] = pd;
            __half2* hp = (__half2*)&g_h1h[gr * HC + h * HID];
#pragma unroll
            for (int c = 0; c < 16; c += 4)
                *(uint4*)&hp[c] = *(uint4*)&hbuf[c];
        }
    }
}

// ---------------- GEMM2 (tensor core): g_h2h @ W2h -> g_g2h + fused alpha2 ----------------
__global__ __launch_bounds__(256) void k_gemm2(const float* __restrict__ a2s,
                                               const float* __restrict__ a2d) {
    const int BM = 128, BN = 64, BK = 32;
    const int LDA = BK + 8;
    const int LDB = BN + 8;
    const int LDC = BN + 8;
    __shared__ __align__(16) __half Ah[BM * LDA];
    __shared__ __align__(16) __half Bh[BK * LDB];
    __shared__ __align__(16) float  Cs[BM * LDC];

    int tid = threadIdx.x;
    int wid = tid >> 5;
    int row0 = blockIdx.x * BM;
    int wm = (wid & 3) * 32;
    int wn = (wid >> 2) * 32;

    wmma::fragment<wmma::accumulator, 16, 16, 16, float> acc[2][2];
#pragma unroll
    for (int i = 0; i < 2; i++)
#pragma unroll
        for (int j = 0; j < 2; j++)
            wmma::fill_fragment(acc[i][j], 0.0f);

    for (int k0 = 0; k0 < HC; k0 += BK) {
#pragma unroll
        for (int q = 0; q < 2; q++) {
            int li = tid * 2 + q;
            int r = li >> 2;
            int c8 = li & 3;
            int gr = row0 + r;
            if (gr > NN - 1) gr = NN - 1;
            *(uint4*)&Ah[r * LDA + c8 * 8] = *(const uint4*)&g_h2h[gr * HC + k0 + c8 * 8];
        }
        {
            int r = tid >> 3;
            int c8 = tid & 7;
            *(uint4*)&Bh[r * LDB + c8 * 8] = *(const uint4*)&g_w2h[(k0 + r) * CLSP + c8 * 8];
        }
        __syncthreads();
#pragma unroll
        for (int kk = 0; kk < BK; kk += 16) {
            wmma::fragment<wmma::matrix_a, 16, 16, 16, __half, wmma::row_major> af[2];
            wmma::fragment<wmma::matrix_b, 16, 16, 16, __half, wmma::row_major> bf[2];
#pragma unroll
            for (int i = 0; i < 2; i++)
                wmma::load_matrix_sync(af[i], &Ah[(wm + i * 16) * LDA + kk], LDA);
#pragma unroll
            for (int j = 0; j < 2; j++)
                wmma::load_matrix_sync(bf[j], &Bh[kk * LDB + wn + j * 16], LDB);
#pragma unroll
            for (int i = 0; i < 2; i++)
#pragma unroll
                for (int j = 0; j < 2; j++)
                    wmma::mma_sync(acc[i][j], af[i], bf[j], acc[i][j]);
        }
        __syncthreads();
    }

#pragma unroll
    for (int i = 0; i < 2; i++)
#pragma unroll
        for (int j = 0; j < 2; j++)
            wmma::store_matrix_sync(&Cs[(wm + i * 16) * LDC + wn + j * 16], acc[i][j],
                                    LDC, wmma::mem_row_major);
    __syncthreads();

    {
        int r = tid >> 1;
        int part = tid & 1;
        int gr = row0 + r;
        const float* crow = &Cs[r * LDC + part * 20];
        if (gr < NN) {
            float ps = 0.0f, pd = 0.0f;
#pragma unroll
            for (int c = 0; c < 20; c++) {
                float v = crow[c];
                int col = part * 20 + c;
                ps += v * a2s[col];
                pd += v * a2d[col];
            }
#pragma unroll
            for (int c = 0; c < 20; c += 2) {
                *(__half2*)&g_g2h[gr * CLS + part * 20 + c] =
                    __float22half2_rn(make_float2(crow[c], crow[c + 1]));
            }
            ps += __shfl_xor_sync(0xffffffffu, ps, 1);
            pd += __shfl_xor_sync(0xffffffffu, pd, 1);
            if (part == 0) {
                g_as2[gr] = ps;
                g_ad2[gr] = pd;
            }
        } else {
            __shfl_xor_sync(0xffffffffu, 0.0f, 1);
            __shfl_xor_sync(0xffffffffu, 0.0f, 1);
        }
    }
}

// ---------------- layer1: online softmax + fp16 gather + bias + ELU -> g_h2h ----------------
// 128 threads per dst node; warp wp covers heads 2wp, 2wp+1 (64 channels = 32 half2).
__global__ __launch_bounds__(128) void k_agg1(const float* __restrict__ b1) {
    int n = blockIdx.x;
    int wp = threadIdx.x >> 5;          // 0..3
    int lane = threadIdx.x & 31;
    int hl = lane >> 4;                 // head within pair
    int h = wp * 2 + hl;
    int el = lane & 15;                 // edge slot within 16-edge chunk
    int beg = g_rowptr[n], end = g_rowptr[n + 1];
    float ad = g_ad1[n * HEADS + h];
    const __half2* __restrict__ h1h2 = (const __half2*)g_h1h;

    float m = -INFINITY, ssum = 0.0f;
    float2 acc = make_float2(0.0f, 0.0f);
    for (int i0 = beg; i0 < end; i0 += 16) {
        int i = i0 + el;
        int sl = 0;
        float e = -INFINITY;
        if (i < end) {
            sl = g_esrc[i];
            e = lrelu(g_as1[sl * HEADS + h] + ad);
        }
        float cm = e;
#pragma unroll
        for (int o = 8; o; o >>= 1) cm = fmaxf(cm, __shfl_xor_sync(0xffffffffu, cm, o));
        float mn = fmaxf(m, cm);
        float sc = __expf(m - mn);
        acc.x *= sc; acc.y *= sc; ssum *= sc;
        m = mn;
        float w = (i < end) ? __expf(e - mn) : 0.0f;
        float ws = w;
#pragma unroll
        for (int o = 8; o; o >>= 1) ws += __shfl_xor_sync(0xffffffffu, ws, o);
        ssum += ws;
        int lim = min(16, end - i0);
        for (int j = 0; j < lim; j++) {
            int   s2 = __shfl_sync(0xffffffffu, sl, j);
            float wj = __shfl_sync(0xffffffffu, w, j + (hl << 4));
            float2 v = __half22float2(h1h2[s2 * (HC / 2) + wp * 32 + lane]);
            acc.x += wj * v.x;
            acc.y += wj * v.y;
        }
    }
    int c0 = wp * 64 + lane * 2;
    float inv_s = 1.0f / ssum;
    float o0 = acc.x * inv_s + b1[c0];
    float o1 = acc.y * inv_s + b1[c0 + 1];
    o0 = (o0 > 0.0f) ? o0 : (__expf(o0) - 1.0f);
    o1 = (o1 > 0.0f) ? o1 : (__expf(o1) - 1.0f);
    *(__half2*)&g_h2h[n * HC + c0] = __float22half2_rn(make_float2(o0, o1));
}

// ---------------- layer2: online softmax + fp16 gather + bias + log_softmax ----------------
__global__ void k_agg2(const float* __restrict__ b2, float* __restrict__ out) {
    int n = blockIdx.x;
    int t = threadIdx.x;
    __shared__ float red[64];
    __shared__ int   s_src[64];
    __shared__ float s_w[64];
    __shared__ float o40[CLS];
    int beg = g_rowptr[n], end = g_rowptr[n + 1];
    float ad = g_ad2[n];
    const __half2* __restrict__ g2h2 = (const __half2*)g_g2h;

    float m = -INFINITY, ssum = 0.0f;
    float2 acc = make_float2(0.0f, 0.0f);
    for (int i0 = beg; i0 < end; i0 += 64) {
        int i = i0 + t;
        int s = 0;
        float e = -INFINITY;
        if (i < end) {
            s = g_esrc[i];
            e = lrelu(g_as2[s] + ad);
        }
        red[t] = e; __syncthreads();
        for (int off = 32; off; off >>= 1) { if (t < off) red[t] = fmaxf(red[t], red[t + off]); __syncthreads(); }
        float mn = fmaxf(m, red[0]);
        __syncthreads();
        float scale = __expf(m - mn);
        acc.x *= scale; acc.y *= scale;
        ssum *= scale;
        m = mn;
        float w = (i < end) ? __expf(e - mn) : 0.0f;
        s_src[t] = s;
        s_w[t] = w;
        red[t] = w; __syncthreads();
        for (int off = 32; off; off >>= 1) { if (t < off) red[t] += red[t + off]; __syncthreads(); }
        ssum += red[0];
        __syncthreads();
        int lim = min(64, end - i0);
        if (t < CLS / 2)
            for (int j = 0; j < lim; j++) {
                float2 v = __half22float2(g2h2[s_src[j] * (CLS / 2) + t]);
                acc.x += s_w[j] * v.x;
                acc.y += s_w[j] * v.y;
            }
        __syncthreads();
    }

    if (t < CLS / 2) {
        float inv_s = 1.0f / ssum;
        o40[t * 2]     = acc.x * inv_s + b2[t * 2];
        o40[t * 2 + 1] = acc.y * inv_s + b2[t * 2 + 1];
    }
    __syncthreads();
    float o = (t < CLS) ? o40[t] : -INFINITY;
    red[t] = o; __syncthreads();
    for (int off = 32; off; off >>= 1) { if (t < off) red[t] = fmaxf(red[t], red[t + off]); __syncthreads(); }
    float mx = red[0]; __syncthreads();
    red[t] = (t < CLS) ? __expf(o - mx) : 0.0f;
    __syncthreads();
    for (int off = 32; off; off >>= 1) { if (t < off) red[t] += red[t + off]; __syncthreads(); }
    if (t < CLS) out[n * CLS + t] = o - mx - logf(red[0]);
}

// ---------------- launch ----------------
extern "C" void kernel_launch(void* const* d_in, const int* in_sizes, int n_in,
                              void* d_out, int out_size) {
    const float* x   = (const float*)d_in[0];
    const int*   ei  = (const int*)d_in[1];      // edge_index is int32 (JAX x64 disabled)
    const float* W1  = (const float*)d_in[2];
    const float* a1s = (const float*)d_in[3];
    const float* a1d = (const float*)d_in[4];
    const float* b1  = (const float*)d_in[5];
    const float* W2  = (const float*)d_in[6];
    const float* a2s = (const float*)d_in[7];
    const float* a2d = (const float*)d_in[8];
    const float* b2  = (const float*)d_in[9];
    float*       out = (float*)d_out;

    // prep: fp16 conversion + CSR build (multi-block scan)
    k_init<<<(NN + 255) / 256, 256>>>();
    k_cvt<<<((NN * FEAT + FEAT * HC + HC * CLSP) / 2 + 255) / 256, 256>>>(x, W1, W2);
    k_count<<<(TOT / 4 + 255) / 256, 256>>>(ei);
    k_bsum<<<NB, 256>>>();
    k_bscan<<<1, 128>>>();
    k_writeptr<<<NB, 256>>>();
    k_scatter<<<(TOT + 255) / 256, 256>>>(ei);

    // layer 1
    k_gemm1<<<dim3((NN + 127) / 128, HC / 64), 256>>>(a1s, a1d);
    k_agg1<<<NN, 128>>>(b1);

    // layer 2
    k_gemm2<<<(NN + 127) / 128, 256>>>(a2s, a2d);
    k_agg2<<<NN, 64>>>(b2, out);
}

// round 15
// speedup vs baseline: 1.6100x; 1.0440x over previous
#include <cuda_runtime.h>
#include <cuda_fp16.h>
#include <mma.h>
#include <math.h>

using namespace nvcuda;

#define NN 20000
#define FEAT 128
#define HID 32
#define HEADS 8
#define HC 256          // HEADS*HID
#define CLS 40
#define CLSP 64         // padded cols for tensor GEMM2
#define E_IN 640000
#define TOT (E_IN + NN)
#define NEG 0.2f
#define NB ((NN + 255) / 256)   // 79 scan blocks

// ---------------- scratch (device globals; no allocation allowed) ----------------
__device__ __half g_xh[NN * FEAT];     // x in fp16
__device__ __half g_w1h[FEAT * HC];    // W1 in fp16
__device__ __half g_w2h[HC * CLSP];    // W2 in fp16, zero-padded to 64 cols
__device__ __half g_h1h[NN * HC];      // layer1 linear output (fp16, for gather)
__device__ __half g_h2h[NN * HC];      // layer1 GAT output after ELU (fp16)
__device__ float  g_as1[NN * HEADS];
__device__ float  g_ad1[NN * HEADS];
__device__ __half g_g2h[NN * CLS];     // layer2 linear output (fp16, for gather)
__device__ float  g_as2[NN];
__device__ float  g_ad2[NN];
__device__ int    g_rowptr[NN + 1];
__device__ int    g_cnt[NN];
__device__ int    g_cur[NN];
__device__ int    g_bsum[128];
__device__ int    g_boff[128];
__device__ int    g_esrc[TOT];         // src node per CSR slot (sorted by dst)

// ---------------- helpers (edge_index is INT32; loads always in-bounds) ----------------
__device__ __forceinline__ int edge_src(const int* ei, int e) {
    int idx = (e < E_IN) ? e : 0;
    int v = ei[idx];
    return (e < E_IN) ? v : (e - E_IN);
}
__device__ __forceinline__ int edge_dst(const int* ei, int e) {
    int idx = (e < E_IN) ? (E_IN + e) : 0;
    int v = ei[idx];
    return (e < E_IN) ? v : (e - E_IN);
}
__device__ __forceinline__ float lrelu(float v) { return v > 0.0f ? v : NEG * v; }

// ---------------- init + fp16 conversion ----------------
__global__ void k_init() {
    int t = blockIdx.x * blockDim.x + threadIdx.x;
    if (t < NN) g_cnt[t] = 0;
}

__global__ void k_cvt(const float* __restrict__ x, const float* __restrict__ W1,
                      const float* __restrict__ W2) {
    int t = blockIdx.x * blockDim.x + threadIdx.x;
    const int NX = NN * FEAT / 2;           // half2 units of x
    const int NW = FEAT * HC / 2;           // half2 units of W1
    const int NW2 = HC * CLSP / 2;          // half2 units of padded W2
    if (t < NX) {
        float2 v = *(const float2*)&x[t * 2];
        *(__half2*)&g_xh[t * 2] = __float22half2_rn(v);
    } else if (t < NX + NW) {
        int u = t - NX;
        float2 v = *(const float2*)&W1[u * 2];
        *(__half2*)&g_w1h[u * 2] = __float22half2_rn(v);
    } else if (t < NX + NW + NW2) {
        int u = t - NX - NW;
        int row = u / (CLSP / 2);
        int cp = (u % (CLSP / 2)) * 2;
        float v0 = (cp < CLS) ? W2[row * CLS + cp] : 0.0f;
        float v1 = (cp + 1 < CLS) ? W2[row * CLS + cp + 1] : 0.0f;
        *(__half2*)&g_w2h[u * 2] = __float22half2_rn(make_float2(v0, v1));
    }
}

// ---------------- CSR build ----------------
__global__ void k_count(const int* __restrict__ ei) {
    int t = blockIdx.x * blockDim.x + threadIdx.x;
    int e0 = t * 4;
    if (e0 >= TOT) return;
    if (e0 + 3 < E_IN) {
        int4 d4 = *(const int4*)&ei[E_IN + e0];
        atomicAdd(&g_cnt[d4.x], 1);
        atomicAdd(&g_cnt[d4.y], 1);
        atomicAdd(&g_cnt[d4.z], 1);
        atomicAdd(&g_cnt[d4.w], 1);
    } else {
        for (int k = 0; k < 4 && e0 + k < TOT; k++)
            atomicAdd(&g_cnt[edge_dst(ei, e0 + k)], 1);
    }
}

// Multi-block scan, phase 1: per-block sums of 256 counts
__global__ void k_bsum() {
    __shared__ int sm[256];
    int t = threadIdx.x;
    int i = blockIdx.x * 256 + t;
    int v = (i < NN) ? g_cnt[i] : 0;
    sm[t] = v;
    __syncthreads();
    for (int off = 128; off; off >>= 1) {
        if (t < off) sm[t] += sm[t + off];
        __syncthreads();
    }
    if (t == 0) g_bsum[blockIdx.x] = sm[0];
}

// phase 2: scan NB block sums (single block of 128)
__global__ void k_bscan() {
    __shared__ int sm[128];
    int t = threadIdx.x;
    int v = (t < NB) ? g_bsum[t] : 0;
    sm[t] = v;
    __syncthreads();
    for (int off = 1; off < 128; off <<= 1) {
        int idx = (t >= off) ? (t - off) : t;
        int add = sm[idx];
        if (t < off) add = 0;
        __syncthreads();
        sm[t] += add;
        __syncthreads();
    }
    if (t < NB) g_boff[t] = sm[t] - v;     // exclusive
    if (t == 127) g_rowptr[NN] = sm[127];
}

// phase 3: per-block exclusive scan + global offset -> rowptr/cur
__global__ void k_writeptr() {
    __shared__ int sm[256];
    int t = threadIdx.x;
    int i = blockIdx.x * 256 + t;
    int v = (i < NN) ? g_cnt[i] : 0;
    sm[t] = v;
    __syncthreads();
    for (int off = 1; off < 256; off <<= 1) {
        int idx = (t >= off) ? (t - off) : t;
        int add = sm[idx];
        if (t < off) add = 0;
        __syncthreads();
        sm[t] += add;
        __syncthreads();
    }
    if (i < NN) {
        int excl = sm[t] - v + g_boff[blockIdx.x];
        g_rowptr[i] = excl;
        g_cur[i] = excl;
    }
}

__global__ void k_scatter(const int* __restrict__ ei) {
    int t = blockIdx.x * blockDim.x + threadIdx.x;
    if (t >= TOT) return;
    int d = edge_dst(ei, t);
    int s = edge_src(ei, t);
    int pos = atomicAdd(&g_cur[d], 1);
    g_esrc[pos] = s;
}

// ---------------- GEMM1 (tensor core): xh @ W1h -> g_h1h + fused alpha1 ----------------
__global__ __launch_bounds__(256) void k_gemm1(const float* __restrict__ a1s,
                                               const float* __restrict__ a1d) {
    const int BM = 128, BN = 64, BK = 32;
    const int LDA = BK + 8;
    const int LDB = BN + 8;
    const int LDC = BN + 8;
    __shared__ __align__(16) __half Ah[BM * LDA];
    __shared__ __align__(16) __half Bh[BK * LDB];
    __shared__ __align__(16) float  Cs[BM * LDC];

    int tid = threadIdx.x;
    int wid = tid >> 5;
    int row0 = blockIdx.x * BM;
    int col0 = blockIdx.y * BN;
    int wm = (wid & 3) * 32;
    int wn = (wid >> 2) * 32;

    wmma::fragment<wmma::accumulator, 16, 16, 16, float> acc[2][2];
#pragma unroll
    for (int i = 0; i < 2; i++)
#pragma unroll
        for (int j = 0; j < 2; j++)
            wmma::fill_fragment(acc[i][j], 0.0f);

    for (int k0 = 0; k0 < FEAT; k0 += BK) {
#pragma unroll
        for (int q = 0; q < 2; q++) {
            int li = tid * 2 + q;
            int r = li >> 2;
            int c8 = li & 3;
            int gr = row0 + r;
            if (gr > NN - 1) gr = NN - 1;
            *(uint4*)&Ah[r * LDA + c8 * 8] = *(const uint4*)&g_xh[gr * FEAT + k0 + c8 * 8];
        }
        {
            int r = tid >> 3;
            int c8 = tid & 7;
            *(uint4*)&Bh[r * LDB + c8 * 8] = *(const uint4*)&g_w1h[(k0 + r) * HC + col0 + c8 * 8];
        }
        __syncthreads();
#pragma unroll
        for (int kk = 0; kk < BK; kk += 16) {
            wmma::fragment<wmma::matrix_a, 16, 16, 16, __half, wmma::row_major> af[2];
            wmma::fragment<wmma::matrix_b, 16, 16, 16, __half, wmma::row_major> bf[2];
#pragma unroll
            for (int i = 0; i < 2; i++)
                wmma::load_matrix_sync(af[i], &Ah[(wm + i * 16) * LDA + kk], LDA);
#pragma unroll
            for (int j = 0; j < 2; j++)
                wmma::load_matrix_sync(bf[j], &Bh[kk * LDB + wn + j * 16], LDB);
#pragma unroll
            for (int i = 0; i < 2; i++)
#pragma unroll
                for (int j = 0; j < 2; j++)
                    wmma::mma_sync(acc[i][j], af[i], bf[j], acc[i][j]);
        }
        __syncthreads();
    }

#pragma unroll
    for (int i = 0; i < 2; i++)
#pragma unroll
        for (int j = 0; j < 2; j++)
            wmma::store_matrix_sync(&Cs[(wm + i * 16) * LDC + wn + j * 16], acc[i][j],
                                    LDC, wmma::mem_row_major);
    __syncthreads();

    {
        int r = tid >> 1;
        int hh = tid & 1;
        int gr = row0 + r;
        int h = blockIdx.y * 2 + hh;
        const float* crow = &Cs[r * LDC + hh * 32];
        if (gr < NN) {
            float ps = 0.0f, pd = 0.0f;
            const float* avs = &a1s[h * HID];
            const float* avd = &a1d[h * HID];
            __half2 hbuf[16];
#pragma unroll
            for (int c = 0; c < 32; c += 2) {
                float v0 = crow[c], v1 = crow[c + 1];
                ps += v0 * avs[c] + v1 * avs[c + 1];
                pd += v0 * avd[c] + v1 * avd[c + 1];
                hbuf[c >> 1] = __float22half2_rn(make_float2(v0, v1));
            }
            g_as1[gr * HEADS + h] = ps;
            g_ad1[gr * HEADS + h] = pd;
            __half2* hp = (__half2*)&g_h1h[gr * HC + h * HID];
#pragma unroll
            for (int c = 0; c < 16; c += 4)
                *(uint4*)&hp[c] = *(uint4*)&hbuf[c];
        }
    }
}

// ---------------- GEMM2 (tensor core): g_h2h @ W2h -> g_g2h + fused alpha2 ----------------
__global__ __launch_bounds__(256) void k_gemm2(const float* __restrict__ a2s,
                                               const float* __restrict__ a2d) {
    const int BM = 128, BN = 64, BK = 32;
    const int LDA = BK + 8;
    const int LDB = BN + 8;
    const int LDC = BN + 8;
    __shared__ __align__(16) __half Ah[BM * LDA];
    __shared__ __align__(16) __half Bh[BK * LDB];
    __shared__ __align__(16) float  Cs[BM * LDC];

    int tid = threadIdx.x;
    int wid = tid >> 5;
    int row0 = blockIdx.x * BM;
    int wm = (wid & 3) * 32;
    int wn = (wid >> 2) * 32;

    wmma::fragment<wmma::accumulator, 16, 16, 16, float> acc[2][2];
#pragma unroll
    for (int i = 0; i < 2; i++)
#pragma unroll
        for (int j = 0; j < 2; j++)
            wmma::fill_fragment(acc[i][j], 0.0f);

    for (int k0 = 0; k0 < HC; k0 += BK) {
#pragma unroll
        for (int q = 0; q < 2; q++) {
            int li = tid * 2 + q;
            int r = li >> 2;
            int c8 = li & 3;
            int gr = row0 + r;
            if (gr > NN - 1) gr = NN - 1;
            *(uint4*)&Ah[r * LDA + c8 * 8] = *(const uint4*)&g_h2h[gr * HC + k0 + c8 * 8];
        }
        {
            int r = tid >> 3;
            int c8 = tid & 7;
            *(uint4*)&Bh[r * LDB + c8 * 8] = *(const uint4*)&g_w2h[(k0 + r) * CLSP + c8 * 8];
        }
        __syncthreads();
#pragma unroll
        for (int kk = 0; kk < BK; kk += 16) {
            wmma::fragment<wmma::matrix_a, 16, 16, 16, __half, wmma::row_major> af[2];
            wmma::fragment<wmma::matrix_b, 16, 16, 16, __half, wmma::row_major> bf[2];
#pragma unroll
            for (int i = 0; i < 2; i++)
                wmma::load_matrix_sync(af[i], &Ah[(wm + i * 16) * LDA + kk], LDA);
#pragma unroll
            for (int j = 0; j < 2; j++)
                wmma::load_matrix_sync(bf[j], &Bh[kk * LDB + wn + j * 16], LDB);
#pragma unroll
            for (int i = 0; i < 2; i++)
#pragma unroll
                for (int j = 0; j < 2; j++)
                    wmma::mma_sync(acc[i][j], af[i], bf[j], acc[i][j]);
        }
        __syncthreads();
    }

#pragma unroll
    for (int i = 0; i < 2; i++)
#pragma unroll
        for (int j = 0; j < 2; j++)
            wmma::store_matrix_sync(&Cs[(wm + i * 16) * LDC + wn + j * 16], acc[i][j],
                                    LDC, wmma::mem_row_major);
    __syncthreads();

    {
        int r = tid >> 1;
        int part = tid & 1;
        int gr = row0 + r;
        const float* crow = &Cs[r * LDC + part * 20];
        if (gr < NN) {
            float ps = 0.0f, pd = 0.0f;
#pragma unroll
            for (int c = 0; c < 20; c++) {
                float v = crow[c];
                int col = part * 20 + c;
                ps += v * a2s[col];
                pd += v * a2d[col];
            }
#pragma unroll
            for (int c = 0; c < 20; c += 2) {
                *(__half2*)&g_g2h[gr * CLS + part * 20 + c] =
                    __float22half2_rn(make_float2(crow[c], crow[c + 1]));
            }
            ps += __shfl_xor_sync(0xffffffffu, ps, 1);
            pd += __shfl_xor_sync(0xffffffffu, pd, 1);
            if (part == 0) {
                g_as2[gr] = ps;
                g_ad2[gr] = pd;
            }
        } else {
            __shfl_xor_sync(0xffffffffu, 0.0f, 1);
            __shfl_xor_sync(0xffffffffu, 0.0f, 1);
        }
    }
}

// ---------------- layer1: online softmax + fp16 gather + bias + ELU -> g_h2h ----------------
// 128 threads per dst node; warp wp covers heads 2wp, 2wp+1 (64 channels = 32 half2).
__global__ __launch_bounds__(128) void k_agg1(const float* __restrict__ b1) {
    int n = blockIdx.x;
    int wp = threadIdx.x >> 5;          // 0..3
    int lane = threadIdx.x & 31;
    int hl = lane >> 4;                 // head within pair
    int h = wp * 2 + hl;
    int el = lane & 15;                 // edge slot within 16-edge chunk
    int beg = g_rowptr[n], end = g_rowptr[n + 1];
    float ad = g_ad1[n * HEADS + h];
    const __half2* __restrict__ h1h2 = (const __half2*)g_h1h;

    float m = -INFINITY, ssum = 0.0f;
    float2 acc = make_float2(0.0f, 0.0f);
    for (int i0 = beg; i0 < end; i0 += 16) {
        int i = i0 + el;
        int sl = 0;
        float e = -INFINITY;
        if (i < end) {
            sl = g_esrc[i];
            e = lrelu(g_as1[sl * HEADS + h] + ad);
        }
        float cm = e;
#pragma unroll
        for (int o = 8; o; o >>= 1) cm = fmaxf(cm, __shfl_xor_sync(0xffffffffu, cm, o));
        float mn = fmaxf(m, cm);
        float sc = __expf(m - mn);
        acc.x *= sc; acc.y *= sc; ssum *= sc;
        m = mn;
        float w = (i < end) ? __expf(e - mn) : 0.0f;
        float ws = w;
#pragma unroll
        for (int o = 8; o; o >>= 1) ws += __shfl_xor_sync(0xffffffffu, ws, o);
        ssum += ws;
        int lim = min(16, end - i0);
        for (int j = 0; j < lim; j++) {
            int   s2 = __shfl_sync(0xffffffffu, sl, j);
            float wj = __shfl_sync(0xffffffffu, w, j + (hl << 4));
            float2 v = __half22float2(h1h2[s2 * (HC / 2) + wp * 32 + lane]);
            acc.x += wj * v.x;
            acc.y += wj * v.y;
        }
    }
    int c0 = wp * 64 + lane * 2;
    float inv_s = 1.0f / ssum;
    float o0 = acc.x * inv_s + b1[c0];
    float o1 = acc.y * inv_s + b1[c0 + 1];
    o0 = (o0 > 0.0f) ? o0 : (__expf(o0) - 1.0f);
    o1 = (o1 > 0.0f) ? o1 : (__expf(o1) - 1.0f);
    *(__half2*)&g_h2h[n * HC + c0] = __float22half2_rn(make_float2(o0, o1));
}

// ---------------- layer2: online softmax + fp16 gather + bias + log_softmax ----------------
__global__ void k_agg2(const float* __restrict__ b2, float* __restrict__ out) {
    int n = blockIdx.x;
    int t = threadIdx.x;
    __shared__ float red[64];
    __shared__ int   s_src[64];
    __shared__ float s_w[64];
    __shared__ float o40[CLS];
    int beg = g_rowptr[n], end = g_rowptr[n + 1];
    float ad = g_ad2[n];
    const __half2* __restrict__ g2h2 = (const __half2*)g_g2h;

    float m = -INFINITY, ssum = 0.0f;
    float2 acc = make_float2(0.0f, 0.0f);
    for (int i0 = beg; i0 < end; i0 += 64) {
        int i = i0 + t;
        int s = 0;
        float e = -INFINITY;
        if (i < end) {
            s = g_esrc[i];
            e = lrelu(g_as2[s] + ad);
        }
        red[t] = e; __syncthreads();
        for (int off = 32; off; off >>= 1) { if (t < off) red[t] = fmaxf(red[t], red[t + off]); __syncthreads(); }
        float mn = fmaxf(m, red[0]);
        __syncthreads();
        float scale = __expf(m - mn);
        acc.x *= scale; acc.y *= scale;
        ssum *= scale;
        m = mn;
        float w = (i < end) ? __expf(e - mn) : 0.0f;
        s_src[t] = s;
        s_w[t] = w;
        red[t] = w; __syncthreads();
        for (int off = 32; off; off >>= 1) { if (t < off) red[t] += red[t + off]; __syncthreads(); }
        ssum += red[0];
        __syncthreads();
        int lim = min(64, end - i0);
        if (t < CLS / 2)
            for (int j = 0; j < lim; j++) {
                float2 v = __half22float2(g2h2[s_src[j] * (CLS / 2) + t]);
                acc.x += s_w[j] * v.x;
                acc.y += s_w[j] * v.y;
            }
        __syncthreads();
    }

    if (t < CLS / 2) {
        float inv_s = 1.0f / ssum;
        o40[t * 2]     = acc.x * inv_s + b2[t * 2];
        o40[t * 2 + 1] = acc.y * inv_s + b2[t * 2 + 1];
    }
    __syncthreads();
    float o = (t < CLS) ? o40[t] : -INFINITY;
    red[t] = o; __syncthreads();
    for (int off = 32; off; off >>= 1) { if (t < off) red[t] = fmaxf(red[t], red[t + off]); __syncthreads(); }
    float mx = red[0]; __syncthreads();
    red[t] = (t < CLS) ? __expf(o - mx) : 0.0f;
    __syncthreads();
    for (int off = 32; off; off >>= 1) { if (t < off) red[t] += red[t + off]; __syncthreads(); }
    if (t < CLS) out[n * CLS + t] = o - mx - logf(red[0]);
}

// ---------------- launch (fork/join: CSR build ∥ cvt+gemm1) ----------------
extern "C" void kernel_launch(void* const* d_in, const int* in_sizes, int n_in,
                              void* d_out, int out_size) {
    const float* x   = (const float*)d_in[0];
    const int*   ei  = (const int*)d_in[1];      // edge_index is int32 (JAX x64 disabled)
    const float* W1  = (const float*)d_in[2];
    const float* a1s = (const float*)d_in[3];
    const float* a1d = (const float*)d_in[4];
    const float* b1  = (const float*)d_in[5];
    const float* W2  = (const float*)d_in[6];
    const float* a2s = (const float*)d_in[7];
    const float* a2d = (const float*)d_in[8];
    const float* b2  = (const float*)d_in[9];
    float*       out = (float*)d_out;

    // one-time host-side objects (no device memory involved)
    static cudaStream_t s2 = nullptr;
    static cudaEvent_t eFork = nullptr, eJoin = nullptr;
    if (!s2) {
        cudaStreamCreateWithFlags(&s2, cudaStreamNonBlocking);
        cudaEventCreateWithFlags(&eFork, cudaEventDisableTiming);
        cudaEventCreateWithFlags(&eJoin, cudaEventDisableTiming);
    }

    // fork: side stream runs the CSR build
    cudaEventRecord(eFork, 0);
    cudaStreamWaitEvent(s2, eFork, 0);

    k_init<<<(NN + 255) / 256, 256, 0, s2>>>();
    k_count<<<(TOT / 4 + 255) / 256, 256, 0, s2>>>(ei);
    k_bsum<<<NB, 256, 0, s2>>>();
    k_bscan<<<1, 128, 0, s2>>>();
    k_writeptr<<<NB, 256, 0, s2>>>();
    k_scatter<<<(TOT + 255) / 256, 256, 0, s2>>>(ei);
    cudaEventRecord(eJoin, s2);

    // main stream: fp16 conversion + GEMM1 (independent of CSR)
    k_cvt<<<((NN * FEAT + FEAT * HC + HC * CLSP) / 2 + 255) / 256, 256>>>(x, W1, W2);
    k_gemm1<<<dim3((NN + 127) / 128, HC / 64), 256>>>(a1s, a1d);

    // join: agg1 needs both branches
    cudaStreamWaitEvent(0, eJoin, 0);
    k_agg1<<<NN, 128>>>(b1);

    // layer 2
    k_gemm2<<<(NN + 127) / 128, 256>>>(a2s, a2d);
    k_agg2<<<NN, 64>>>(b2, out);
}

// round 16
// speedup vs baseline: 1.6211x; 1.0069x over previous
#include <cuda_runtime.h>
#include <cuda_fp16.h>
#include <mma.h>
#include <math.h>

using namespace nvcuda;

#define NN 20000
#define FEAT 128
#define HID 32
#define HEADS 8
#define HC 256          // HEADS*HID
#define CLS 40
#define CLSP 64         // padded cols for tensor GEMM2
#define E_IN 640000
#define TOT (E_IN + NN)
#define NEG 0.2f
#define NB ((NN + 255) / 256)   // 79 scan blocks

// ---------------- scratch (device globals; no allocation allowed) ----------------
__device__ __half g_xh[NN * FEAT];     // x in fp16
__device__ __half g_w1h[FEAT * HC];    // W1 in fp16
__device__ __half g_w2h[HC * CLSP];    // W2 in fp16, zero-padded to 64 cols
__device__ __half g_h1h[NN * HC];      // layer1 linear output (fp16, for gather)
__device__ __half g_h2h[NN * HC];      // layer1 GAT output after ELU (fp16)
__device__ float  g_as1[NN * HEADS];
__device__ float  g_ad1[NN * HEADS];
__device__ __half g_g2h[NN * CLS];     // layer2 linear output (fp16, for gather)
__device__ float  g_as2[NN];
__device__ float  g_ad2[NN];
__device__ int    g_rowptr[NN + 1];
__device__ int    g_cnt[NN];           // zero-init at load; re-zeroed by k_writeptr
__device__ int    g_cur[NN];
__device__ int    g_bsum[128];
__device__ int    g_boff[128];
__device__ int    g_done;              // zero-init; reset by last bsum block
__device__ int    g_esrc[TOT];         // src node per CSR slot (sorted by dst)

// ---------------- helpers (edge_index is INT32; loads always in-bounds) ----------------
__device__ __forceinline__ int edge_src(const int* ei, int e) {
    int idx = (e < E_IN) ? e : 0;
    int v = ei[idx];
    return (e < E_IN) ? v : (e - E_IN);
}
__device__ __forceinline__ int edge_dst(const int* ei, int e) {
    int idx = (e < E_IN) ? (E_IN + e) : 0;
    int v = ei[idx];
    return (e < E_IN) ? v : (e - E_IN);
}
__device__ __forceinline__ float lrelu(float v) { return v > 0.0f ? v : NEG * v; }

// ---------------- fp16 conversion ----------------
__global__ void k_cvt(const float* __restrict__ x, const float* __restrict__ W1,
                      const float* __restrict__ W2) {
    int t = blockIdx.x * blockDim.x + threadIdx.x;
    const int NX = NN * FEAT / 2;           // half2 units of x
    const int NW = FEAT * HC / 2;           // half2 units of W1
    const int NW2 = HC * CLSP / 2;          // half2 units of padded W2
    if (t < NX) {
        float2 v = *(const float2*)&x[t * 2];
        *(__half2*)&g_xh[t * 2] = __float22half2_rn(v);
    } else if (t < NX + NW) {
        int u = t - NX;
        float2 v = *(const float2*)&W1[u * 2];
        *(__half2*)&g_w1h[u * 2] = __float22half2_rn(v);
    } else if (t < NX + NW + NW2) {
        int u = t - NX - NW;
        int row = u / (CLSP / 2);
        int cp = (u % (CLSP / 2)) * 2;
        float v0 = (cp < CLS) ? W2[row * CLS + cp] : 0.0f;
        float v1 = (cp + 1 < CLS) ? W2[row * CLS + cp + 1] : 0.0f;
        *(__half2*)&g_w2h[u * 2] = __float22half2_rn(make_float2(v0, v1));
    }
}

// ---------------- CSR build ----------------
__global__ void k_count(const int* __restrict__ ei) {
    int t = blockIdx.x * blockDim.x + threadIdx.x;
    int e0 = t * 4;
    if (e0 >= TOT) return;
    if (e0 + 3 < E_IN) {
        int4 d4 = *(const int4*)&ei[E_IN + e0];
        atomicAdd(&g_cnt[d4.x], 1);
        atomicAdd(&g_cnt[d4.y], 1);
        atomicAdd(&g_cnt[d4.z], 1);
        atomicAdd(&g_cnt[d4.w], 1);
    } else {
        for (int k = 0; k < 4 && e0 + k < TOT; k++)
            atomicAdd(&g_cnt[edge_dst(ei, e0 + k)], 1);
    }
}

// Fused: per-block sums + last-block scan of the NB block sums.
__global__ void k_bsum() {
    __shared__ int sm[256];
    __shared__ int isLast;
    int t = threadIdx.x;
    int i = blockIdx.x * 256 + t;
    int v = (i < NN) ? g_cnt[i] : 0;
    sm[t] = v;
    __syncthreads();
    for (int off = 128; off; off >>= 1) {
        if (t < off) sm[t] += sm[t + off];
        __syncthreads();
    }
    if (t == 0) {
        g_bsum[blockIdx.x] = sm[0];
        __threadfence();
        int prev = atomicAdd(&g_done, 1);
        isLast = (prev == NB - 1);
    }
    __syncthreads();
    if (!isLast) return;

    // last block: exclusive scan of NB sums (first 128 threads)
    if (t < 128) {
        int sv = (t < NB) ? g_bsum[t] : 0;
        sm[t] = sv;
        __syncthreads();
        for (int off = 1; off < 128; off <<= 1) {
            int idx = (t >= off) ? (t - off) : t;
            int add = sm[idx];
            if (t < off) add = 0;
            __syncthreads();
            sm[t] += add;
            __syncthreads();
        }
        if (t < NB) g_boff[t] = sm[t] - sv;    // exclusive
        if (t == 127) {
            g_rowptr[NN] = sm[127];
            g_done = 0;                         // reset for next replay
        }
    }
}

// per-block exclusive scan + global offset -> rowptr/cur; re-zero g_cnt for next run
__global__ void k_writeptr() {
    __shared__ int sm[256];
    int t = threadIdx.x;
    int i = blockIdx.x * 256 + t;
    int v = (i < NN) ? g_cnt[i] : 0;
    sm[t] = v;
    __syncthreads();
    for (int off = 1; off < 256; off <<= 1) {
        int idx = (t >= off) ? (t - off) : t;
        int add = sm[idx];
        if (t < off) add = 0;
        __syncthreads();
        sm[t] += add;
        __syncthreads();
    }
    if (i < NN) {
        int excl = sm[t] - v + g_boff[blockIdx.x];
        g_rowptr[i] = excl;
        g_cur[i] = excl;
        g_cnt[i] = 0;                           // ready for next replay
    }
}

__global__ void k_scatter(const int* __restrict__ ei) {
    int t = blockIdx.x * blockDim.x + threadIdx.x;
    if (t >= TOT) return;
    int d = edge_dst(ei, t);
    int s = edge_src(ei, t);
    int pos = atomicAdd(&g_cur[d], 1);
    g_esrc[pos] = s;
}

// ---------------- GEMM1 (tensor core): xh @ W1h -> g_h1h + fused alpha1 ----------------
__global__ __launch_bounds__(256) void k_gemm1(const float* __restrict__ a1s,
                                               const float* __restrict__ a1d) {
    const int BM = 128, BN = 64, BK = 32;
    const int LDA = BK + 8;
    const int LDB = BN + 8;
    const int LDC = BN + 8;
    __shared__ __align__(16) __half Ah[BM * LDA];
    __shared__ __align__(16) __half Bh[BK * LDB];
    __shared__ __align__(16) float  Cs[BM * LDC];

    int tid = threadIdx.x;
    int wid = tid >> 5;
    int row0 = blockIdx.x * BM;
    int col0 = blockIdx.y * BN;
    int wm = (wid & 3) * 32;
    int wn = (wid >> 2) * 32;

    wmma::fragment<wmma::accumulator, 16, 16, 16, float> acc[2][2];
#pragma unroll
    for (int i = 0; i < 2; i++)
#pragma unroll
        for (int j = 0; j < 2; j++)
            wmma::fill_fragment(acc[i][j], 0.0f);

    for (int k0 = 0; k0 < FEAT; k0 += BK) {
#pragma unroll
        for (int q = 0; q < 2; q++) {
            int li = tid * 2 + q;
            int r = li >> 2;
            int c8 = li & 3;
            int gr = row0 + r;
            if (gr > NN - 1) gr = NN - 1;
            *(uint4*)&Ah[r * LDA + c8 * 8] = *(const uint4*)&g_xh[gr * FEAT + k0 + c8 * 8];
        }
        {
            int r = tid >> 3;
            int c8 = tid & 7;
            *(uint4*)&Bh[r * LDB + c8 * 8] = *(const uint4*)&g_w1h[(k0 + r) * HC + col0 + c8 * 8];
        }
        __syncthreads();
#pragma unroll
        for (int kk = 0; kk < BK; kk += 16) {
            wmma::fragment<wmma::matrix_a, 16, 16, 16, __half, wmma::row_major> af[2];
            wmma::fragment<wmma::matrix_b, 16, 16, 16, __half, wmma::row_major> bf[2];
#pragma unroll
            for (int i = 0; i < 2; i++)
                wmma::load_matrix_sync(af[i], &Ah[(wm + i * 16) * LDA + kk], LDA);
#pragma unroll
            for (int j = 0; j < 2; j++)
                wmma::load_matrix_sync(bf[j], &Bh[kk * LDB + wn + j * 16], LDB);
#pragma unroll
            for (int i = 0; i < 2; i++)
#pragma unroll
                for (int j = 0; j < 2; j++)
                    wmma::mma_sync(acc[i][j], af[i], bf[j], acc[i][j]);
        }
        __syncthreads();
    }

#pragma unroll
    for (int i = 0; i < 2; i++)
#pragma unroll
        for (int j = 0; j < 2; j++)
            wmma::store_matrix_sync(&Cs[(wm + i * 16) * LDC + wn + j * 16], acc[i][j],
                                    LDC, wmma::mem_row_major);
    __syncthreads();

    {
        int r = tid >> 1;
        int hh = tid & 1;
        int gr = row0 + r;
        int h = blockIdx.y * 2 + hh;
        const float* crow = &Cs[r * LDC + hh * 32];
        if (gr < NN) {
            float ps = 0.0f, pd = 0.0f;
            const float* avs = &a1s[h * HID];
            const float* avd = &a1d[h * HID];
            __half2 hbuf[16];
#pragma unroll
            for (int c = 0; c < 32; c += 2) {
                float v0 = crow[c], v1 = crow[c + 1];
                ps += v0 * avs[c] + v1 * avs[c + 1];
                pd += v0 * avd[c] + v1 * avd[c + 1];
                hbuf[c >> 1] = __float22half2_rn(make_float2(v0, v1));
            }
            g_as1[gr * HEADS + h] = ps;
            g_ad1[gr * HEADS + h] = pd;
            __half2* hp = (__half2*)&g_h1h[gr * HC + h * HID];
#pragma unroll
            for (int c = 0; c < 16; c += 4)
                *(uint4*)&hp[c] = *(uint4*)&hbuf[c];
        }
    }
}

// ---------------- GEMM2 (tensor core): g_h2h @ W2h -> g_g2h + fused alpha2 ----------------
__global__ __launch_bounds__(256) void k_gemm2(const float* __restrict__ a2s,
                                               const float* __restrict__ a2d) {
    const int BM = 128, BN = 64, BK = 32;
    const int LDA = BK + 8;
    const int LDB = BN + 8;
    const int LDC = BN + 8;
    __shared__ __align__(16) __half Ah[BM * LDA];
    __shared__ __align__(16) __half Bh[BK * LDB];
    __shared__ __align__(16) float  Cs[BM * LDC];

    int tid = threadIdx.x;
    int wid = tid >> 5;
    int row0 = blockIdx.x * BM;
    int wm = (wid & 3) * 32;
    int wn = (wid >> 2) * 32;

    wmma::fragment<wmma::accumulator, 16, 16, 16, float> acc[2][2];
#pragma unroll
    for (int i = 0; i < 2; i++)
#pragma unroll
        for (int j = 0; j < 2; j++)
            wmma::fill_fragment(acc[i][j], 0.0f);

    for (int k0 = 0; k0 < HC; k0 += BK) {
#pragma unroll
        for (int q = 0; q < 2; q++) {
            int li = tid * 2 + q;
            int r = li >> 2;
            int c8 = li & 3;
            int gr = row0 + r;
            if (gr > NN - 1) gr = NN - 1;
            *(uint4*)&Ah[r * LDA + c8 * 8] = *(const uint4*)&g_h2h[gr * HC + k0 + c8 * 8];
        }
        {
            int r = tid >> 3;
            int c8 = tid & 7;
            *(uint4*)&Bh[r * LDB + c8 * 8] = *(const uint4*)&g_w2h[(k0 + r) * CLSP + c8 * 8];
        }
        __syncthreads();
#pragma unroll
        for (int kk = 0; kk < BK; kk += 16) {
            wmma::fragment<wmma::matrix_a, 16, 16, 16, __half, wmma::row_major> af[2];
            wmma::fragment<wmma::matrix_b, 16, 16, 16, __half, wmma::row_major> bf[2];
#pragma unroll
            for (int i = 0; i < 2; i++)
                wmma::load_matrix_sync(af[i], &Ah[(wm + i * 16) * LDA + kk], LDA);
#pragma unroll
            for (int j = 0; j < 2; j++)
                wmma::load_matrix_sync(bf[j], &Bh[kk * LDB + wn + j * 16], LDB);
#pragma unroll
            for (int i = 0; i < 2; i++)
#pragma unroll
                for (int j = 0; j < 2; j++)
                    wmma::mma_sync(acc[i][j], af[i], bf[j], acc[i][j]);
        }
        __syncthreads();
    }

#pragma unroll
    for (int i = 0; i < 2; i++)
#pragma unroll
        for (int j = 0; j < 2; j++)
            wmma::store_matrix_sync(&Cs[(wm + i * 16) * LDC + wn + j * 16], acc[i][j],
                                    LDC, wmma::mem_row_major);
    __syncthreads();

    {
        int r = tid >> 1;
        int part = tid & 1;
        int gr = row0 + r;
        const float* crow = &Cs[r * LDC + part * 20];
        if (gr < NN) {
            float ps = 0.0f, pd = 0.0f;
#pragma unroll
            for (int c = 0; c < 20; c++) {
                float v = crow[c];
                int col = part * 20 + c;
                ps += v * a2s[col];
                pd += v * a2d[col];
            }
#pragma unroll
            for (int c = 0; c < 20; c += 2) {
                *(__half2*)&g_g2h[gr * CLS + part * 20 + c] =
                    __float22half2_rn(make_float2(crow[c], crow[c + 1]));
            }
            ps += __shfl_xor_sync(0xffffffffu, ps, 1);
            pd += __shfl_xor_sync(0xffffffffu, pd, 1);
            if (part == 0) {
                g_as2[gr] = ps;
                g_ad2[gr] = pd;
            }
        } else {
            __shfl_xor_sync(0xffffffffu, 0.0f, 1);
            __shfl_xor_sync(0xffffffffu, 0.0f, 1);
        }
    }
}

// ---------------- layer1: online softmax + fp16 gather + bias + ELU -> g_h2h ----------------
// 128 threads per dst node; warp wp covers heads 2wp, 2wp+1 (64 channels = 32 half2).
__global__ __launch_bounds__(128) void k_agg1(const float* __restrict__ b1) {
    int n = blockIdx.x;
    int wp = threadIdx.x >> 5;          // 0..3
    int lane = threadIdx.x & 31;
    int hl = lane >> 4;                 // head within pair
    int h = wp * 2 + hl;
    int el = lane & 15;                 // edge slot within 16-edge chunk
    int beg = g_rowptr[n], end = g_rowptr[n + 1];
    float ad = g_ad1[n * HEADS + h];
    const __half2* __restrict__ h1h2 = (const __half2*)g_h1h;

    float m = -INFINITY, ssum = 0.0f;
    float2 acc = make_float2(0.0f, 0.0f);
    for (int i0 = beg; i0 < end; i0 += 16) {
        int i = i0 + el;
        int sl = 0;
        float e = -INFINITY;
        if (i < end) {
            sl = g_esrc[i];
            e = lrelu(g_as1[sl * HEADS + h] + ad);
        }
        float cm = e;
#pragma unroll
        for (int o = 8; o; o >>= 1) cm = fmaxf(cm, __shfl_xor_sync(0xffffffffu, cm, o));
        float mn = fmaxf(m, cm);
        float sc = __expf(m - mn);
        acc.x *= sc; acc.y *= sc; ssum *= sc;
        m = mn;
        float w = (i < end) ? __expf(e - mn) : 0.0f;
        float ws = w;
#pragma unroll
        for (int o = 8; o; o >>= 1) ws += __shfl_xor_sync(0xffffffffu, ws, o);
        ssum += ws;
        int lim = min(16, end - i0);
        for (int j = 0; j < lim; j++) {
            int   s2 = __shfl_sync(0xffffffffu, sl, j);
            float wj = __shfl_sync(0xffffffffu, w, j + (hl << 4));
            float2 v = __half22float2(h1h2[s2 * (HC / 2) + wp * 32 + lane]);
            acc.x += wj * v.x;
            acc.y += wj * v.y;
        }
    }
    int c0 = wp * 64 + lane * 2;
    float inv_s = 1.0f / ssum;
    float o0 = acc.x * inv_s + b1[c0];
    float o1 = acc.y * inv_s + b1[c0 + 1];
    o0 = (o0 > 0.0f) ? o0 : (__expf(o0) - 1.0f);
    o1 = (o1 > 0.0f) ? o1 : (__expf(o1) - 1.0f);
    *(__half2*)&g_h2h[n * HC + c0] = __float22half2_rn(make_float2(o0, o1));
}

// ---------------- layer2: online softmax + fp16 gather + bias + log_softmax ----------------
__global__ void k_agg2(const float* __restrict__ b2, float* __restrict__ out) {
    int n = blockIdx.x;
    int t = threadIdx.x;
    __shared__ float red[64];
    __shared__ int   s_src[64];
    __shared__ float s_w[64];
    __shared__ float o40[CLS];
    int beg = g_rowptr[n], end = g_rowptr[n + 1];
    float ad = g_ad2[n];
    const __half2* __restrict__ g2h2 = (const __half2*)g_g2h;

    float m = -INFINITY, ssum = 0.0f;
    float2 acc = make_float2(0.0f, 0.0f);
    for (int i0 = beg; i0 < end; i0 += 64) {
        int i = i0 + t;
        int s = 0;
        float e = -INFINITY;
        if (i < end) {
            s = g_esrc[i];
            e = lrelu(g_as2[s] + ad);
        }
        red[t] = e; __syncthreads();
        for (int off = 32; off; off >>= 1) { if (t < off) red[t] = fmaxf(red[t], red[t + off]); __syncthreads(); }
        float mn = fmaxf(m, red[0]);
        __syncthreads();
        float scale = __expf(m - mn);
        acc.x *= scale; acc.y *= scale;
        ssum *= scale;
        m = mn;
        float w = (i < end) ? __expf(e - mn) : 0.0f;
        s_src[t] = s;
        s_w[t] = w;
        red[t] = w; __syncthreads();
        for (int off = 32; off; off >>= 1) { if (t < off) red[t] += red[t + off]; __syncthreads(); }
        ssum += red[0];
        __syncthreads();
        int lim = min(64, end - i0);
        if (t < CLS / 2)
            for (int j = 0; j < lim; j++) {
                float2 v = __half22float2(g2h2[s_src[j] * (CLS / 2) + t]);
                acc.x += s_w[j] * v.x;
                acc.y += s_w[j] * v.y;
            }
        __syncthreads();
    }

    if (t < CLS / 2) {
        float inv_s = 1.0f / ssum;
        o40[t * 2]     = acc.x * inv_s + b2[t * 2];
        o40[t * 2 + 1] = acc.y * inv_s + b2[t * 2 + 1];
    }
    __syncthreads();
    float o = (t < CLS) ? o40[t] : -INFINITY;
    red[t] = o; __syncthreads();
    for (int off = 32; off; off >>= 1) { if (t < off) red[t] = fmaxf(red[t], red[t + off]); __syncthreads(); }
    float mx = red[0]; __syncthreads();
    red[t] = (t < CLS) ? __expf(o - mx) : 0.0f;
    __syncthreads();
    for (int off = 32; off; off >>= 1) { if (t < off) red[t] += red[t + off]; __syncthreads(); }
    if (t < CLS) out[n * CLS + t] = o - mx - logf(red[0]);
}

// ---------------- launch (fork/join: CSR build ∥ cvt+gemm1) ----------------
extern "C" void kernel_launch(void* const* d_in, const int* in_sizes, int n_in,
                              void* d_out, int out_size) {
    const float* x   = (const float*)d_in[0];
    const int*   ei  = (const int*)d_in[1];      // edge_index is int32 (JAX x64 disabled)
    const float* W1  = (const float*)d_in[2];
    const float* a1s = (const float*)d_in[3];
    const float* a1d = (const float*)d_in[4];
    const float* b1  = (const float*)d_in[5];
    const float* W2  = (const float*)d_in[6];
    const float* a2s = (const float*)d_in[7];
    const float* a2d = (const float*)d_in[8];
    const float* b2  = (const float*)d_in[9];
    float*       out = (float*)d_out;

    // one-time host-side objects (no device memory involved)
    static cudaStream_t s2 = nullptr;
    static cudaEvent_t eFork = nullptr, eJoin = nullptr;
    if (!s2) {
        cudaStreamCreateWithFlags(&s2, cudaStreamNonBlocking);
        cudaEventCreateWithFlags(&eFork, cudaEventDisableTiming);
        cudaEventCreateWithFlags(&eJoin, cudaEventDisableTiming);
    }

    // fork: side stream runs the CSR build (g_cnt/g_done are pre-zeroed:
    // zero-init at load, re-zeroed by k_writeptr / last k_bsum block each run)
    cudaEventRecord(eFork, 0);
    cudaStreamWaitEvent(s2, eFork, 0);

    k_count<<<(TOT / 4 + 255) / 256, 256, 0, s2>>>(ei);
    k_bsum<<<NB, 256, 0, s2>>>();
    k_writeptr<<<NB, 256, 0, s2>>>();
    k_scatter<<<(TOT + 255) / 256, 256, 0, s2>>>(ei);
    cudaEventRecord(eJoin, s2);

    // main stream: fp16 conversion + GEMM1 (independent of CSR)
    k_cvt<<<((NN * FEAT + FEAT * HC + HC * CLSP) / 2 + 255) / 256, 256>>>(x, W1, W2);
    k_gemm1<<<dim3((NN + 127) / 128, HC / 64), 256>>>(a1s, a1d);

    // join: agg1 needs both branches
    cudaStreamWaitEvent(0, eJoin, 0);
    k_agg1<<<NN, 128>>>(b1);

    // layer 2
    k_gemm2<<<(NN + 127) / 128, 256>>>(a2s, a2d);
    k_agg2<<<NN, 64>>>(b2, out);
}

// round 17
// speedup vs baseline: 1.6273x; 1.0038x over previous
#include <cuda_runtime.h>
#include <cuda_fp16.h>
#include <mma.h>
#include <math.h>

using namespace nvcuda;

#define NN 20000
#define FEAT 128
#define HID 32
#define HEADS 8
#define HC 256          // HEADS*HID
#define CLS 40
#define CLSP 64         // padded cols for tensor GEMM2
#define E_IN 640000
#define TOT (E_IN + NN)
#define NEG 0.2f
#define NB ((NN + 255) / 256)   // 79 scan blocks

// ---------------- scratch (device globals; no allocation allowed) ----------------
__device__ __half g_xh[NN * FEAT];     // x in fp16
__device__ __half g_w1h[FEAT * HC];    // W1 in fp16
__device__ __half g_w2h[HC * CLSP];    // W2 in fp16, zero-padded to 64 cols
__device__ __half g_h1h[NN * HC];      // layer1 linear output (fp16, for gather)
__device__ __half g_h2h[NN * HC];      // layer1 GAT output after ELU (fp16)
__device__ float  g_as1[NN * HEADS];
__device__ float  g_ad1[NN * HEADS];
__device__ __half g_g2h[NN * CLS];     // layer2 linear output (fp16, for gather)
__device__ float  g_as2[NN];
__device__ float  g_ad2[NN];
__device__ int    g_rowptr[NN + 1];
__device__ int    g_cnt[NN];           // zero-init at load; re-zeroed by k_writeptr
__device__ int    g_erank[TOT];        // within-dst rank of each edge (from k_count)
__device__ int    g_bsum[128];
__device__ int    g_boff[128];
__device__ int    g_done;              // zero-init; reset by last bsum block
__device__ int    g_esrc[TOT];         // src node per CSR slot (sorted by dst)

// ---------------- helpers (edge_index is INT32; loads always in-bounds) ----------------
__device__ __forceinline__ int edge_src(const int* ei, int e) {
    int idx = (e < E_IN) ? e : 0;
    int v = ei[idx];
    return (e < E_IN) ? v : (e - E_IN);
}
__device__ __forceinline__ int edge_dst(const int* ei, int e) {
    int idx = (e < E_IN) ? (E_IN + e) : 0;
    int v = ei[idx];
    return (e < E_IN) ? v : (e - E_IN);
}
__device__ __forceinline__ float lrelu(float v) { return v > 0.0f ? v : NEG * v; }

// ---------------- fp16 conversion ----------------
__global__ void k_cvt(const float* __restrict__ x, const float* __restrict__ W1,
                      const float* __restrict__ W2) {
    int t = blockIdx.x * blockDim.x + threadIdx.x;
    const int NX = NN * FEAT / 2;           // half2 units of x
    const int NW = FEAT * HC / 2;           // half2 units of W1
    const int NW2 = HC * CLSP / 2;          // half2 units of padded W2
    if (t < NX) {
        float2 v = *(const float2*)&x[t * 2];
        *(__half2*)&g_xh[t * 2] = __float22half2_rn(v);
    } else if (t < NX + NW) {
        int u = t - NX;
        float2 v = *(const float2*)&W1[u * 2];
        *(__half2*)&g_w1h[u * 2] = __float22half2_rn(v);
    } else if (t < NX + NW + NW2) {
        int u = t - NX - NW;
        int row = u / (CLSP / 2);
        int cp = (u % (CLSP / 2)) * 2;
        float v0 = (cp < CLS) ? W2[row * CLS + cp] : 0.0f;
        float v1 = (cp + 1 < CLS) ? W2[row * CLS + cp + 1] : 0.0f;
        *(__half2*)&g_w2h[u * 2] = __float22half2_rn(make_float2(v0, v1));
    }
}

// ---------------- CSR build ----------------
// count + within-dst rank assignment (rank = old count value)
__global__ void k_count(const int* __restrict__ ei) {
    int t = blockIdx.x * blockDim.x + threadIdx.x;
    int e0 = t * 4;
    if (e0 >= TOT) return;
    if (e0 + 3 < E_IN) {
        int4 d4 = *(const int4*)&ei[E_IN + e0];
        int4 r4;
        r4.x = atomicAdd(&g_cnt[d4.x], 1);
        r4.y = atomicAdd(&g_cnt[d4.y], 1);
        r4.z = atomicAdd(&g_cnt[d4.z], 1);
        r4.w = atomicAdd(&g_cnt[d4.w], 1);
        *(int4*)&g_erank[e0] = r4;
    } else {
        for (int k = 0; k < 4 && e0 + k < TOT; k++)
            g_erank[e0 + k] = atomicAdd(&g_cnt[edge_dst(ei, e0 + k)], 1);
    }
}

// Fused: per-block sums + last-block scan of the NB block sums.
__global__ void k_bsum() {
    __shared__ int sm[256];
    __shared__ int isLast;
    int t = threadIdx.x;
    int i = blockIdx.x * 256 + t;
    int v = (i < NN) ? g_cnt[i] : 0;
    sm[t] = v;
    __syncthreads();
    for (int off = 128; off; off >>= 1) {
        if (t < off) sm[t] += sm[t + off];
        __syncthreads();
    }
    if (t == 0) {
        g_bsum[blockIdx.x] = sm[0];
        __threadfence();
        int prev = atomicAdd(&g_done, 1);
        isLast = (prev == NB - 1);
    }
    __syncthreads();
    if (!isLast) return;

    // last block: exclusive scan of NB sums (first 128 threads)
    if (t < 128) {
        int sv = (t < NB) ? g_bsum[t] : 0;
        sm[t] = sv;
        __syncthreads();
        for (int off = 1; off < 128; off <<= 1) {
            int idx = (t >= off) ? (t - off) : t;
            int add = sm[idx];
            if (t < off) add = 0;
            __syncthreads();
            sm[t] += add;
            __syncthreads();
        }
        if (t < NB) g_boff[t] = sm[t] - sv;    // exclusive
        if (t == 127) {
            g_rowptr[NN] = sm[127];
            g_done = 0;                         // reset for next replay
        }
    }
}

// per-block exclusive scan + global offset -> rowptr; re-zero g_cnt for next run
__global__ void k_writeptr() {
    __shared__ int sm[256];
    int t = threadIdx.x;
    int i = blockIdx.x * 256 + t;
    int v = (i < NN) ? g_cnt[i] : 0;
    sm[t] = v;
    __syncthreads();
    for (int off = 1; off < 256; off <<= 1) {
        int idx = (t >= off) ? (t - off) : t;
        int add = sm[idx];
        if (t < off) add = 0;
        __syncthreads();
        sm[t] += add;
        __syncthreads();
    }
    if (i < NN) {
        g_rowptr[i] = sm[t] - v + g_boff[blockIdx.x];
        g_cnt[i] = 0;                           // ready for next replay
    }
}

// atomic-free scatter: position = rowptr[dst] + precomputed rank
__global__ void k_scatter(const int* __restrict__ ei) {
    int t = blockIdx.x * blockDim.x + threadIdx.x;
    if (t >= TOT) return;
    int d = edge_dst(ei, t);
    int s = edge_src(ei, t);
    g_esrc[g_rowptr[d] + g_erank[t]] = s;
}

// ---------------- GEMM1 (tensor core): xh @ W1h -> g_h1h + fused alpha1 ----------------
__global__ __launch_bounds__(256) void k_gemm1(const float* __restrict__ a1s,
                                               const float* __restrict__ a1d) {
    const int BM = 128, BN = 64, BK = 32;
    const int LDA = BK + 8;
    const int LDB = BN + 8;
    const int LDC = BN + 8;
    __shared__ __align__(16) __half Ah[BM * LDA];
    __shared__ __align__(16) __half Bh[BK * LDB];
    __shared__ __align__(16) float  Cs[BM * LDC];

    int tid = threadIdx.x;
    int wid = tid >> 5;
    int row0 = blockIdx.x * BM;
    int col0 = blockIdx.y * BN;
    int wm = (wid & 3) * 32;
    int wn = (wid >> 2) * 32;

    wmma::fragment<wmma::accumulator, 16, 16, 16, float> acc[2][2];
#pragma unroll
    for (int i = 0; i < 2; i++)
#pragma unroll
        for (int j = 0; j < 2; j++)
            wmma::fill_fragment(acc[i][j], 0.0f);

    for (int k0 = 0; k0 < FEAT; k0 += BK) {
#pragma unroll
        for (int q = 0; q < 2; q++) {
            int li = tid * 2 + q;
            int r = li >> 2;
            int c8 = li & 3;
            int gr = row0 + r;
            if (gr > NN - 1) gr = NN - 1;
            *(uint4*)&Ah[r * LDA + c8 * 8] = *(const uint4*)&g_xh[gr * FEAT + k0 + c8 * 8];
        }
        {
            int r = tid >> 3;
            int c8 = tid & 7;
            *(uint4*)&Bh[r * LDB + c8 * 8] = *(const uint4*)&g_w1h[(k0 + r) * HC + col0 + c8 * 8];
        }
        __syncthreads();
#pragma unroll
        for (int kk = 0; kk < BK; kk += 16) {
            wmma::fragment<wmma::matrix_a, 16, 16, 16, __half, wmma::row_major> af[2];
            wmma::fragment<wmma::matrix_b, 16, 16, 16, __half, wmma::row_major> bf[2];
#pragma unroll
            for (int i = 0; i < 2; i++)
                wmma::load_matrix_sync(af[i], &Ah[(wm + i * 16) * LDA + kk], LDA);
#pragma unroll
            for (int j = 0; j < 2; j++)
                wmma::load_matrix_sync(bf[j], &Bh[kk * LDB + wn + j * 16], LDB);
#pragma unroll
            for (int i = 0; i < 2; i++)
#pragma unroll
                for (int j = 0; j < 2; j++)
                    wmma::mma_sync(acc[i][j], af[i], bf[j], acc[i][j]);
        }
        __syncthreads();
    }

#pragma unroll
    for (int i = 0; i < 2; i++)
#pragma unroll
        for (int j = 0; j < 2; j++)
            wmma::store_matrix_sync(&Cs[(wm + i * 16) * LDC + wn + j * 16], acc[i][j],
                                    LDC, wmma::mem_row_major);
    __syncthreads();

    {
        int r = tid >> 1;
        int hh = tid & 1;
        int gr = row0 + r;
        int h = blockIdx.y * 2 + hh;
        const float* crow = &Cs[r * LDC + hh * 32];
        if (gr < NN) {
            float ps = 0.0f, pd = 0.0f;
            const float* avs = &a1s[h * HID];
            const float* avd = &a1d[h * HID];
            __half2 hbuf[16];
#pragma unroll
            for (int c = 0; c < 32; c += 2) {
                float v0 = crow[c], v1 = crow[c + 1];
                ps += v0 * avs[c] + v1 * avs[c + 1];
                pd += v0 * avd[c] + v1 * avd[c + 1];
                hbuf[c >> 1] = __float22half2_rn(make_float2(v0, v1));
            }
            g_as1[gr * HEADS + h] = ps;
            g_ad1[gr * HEADS + h] = pd;
            __half2* hp = (__half2*)&g_h1h[gr * HC + h * HID];
#pragma unroll
            for (int c = 0; c < 16; c += 4)
                *(uint4*)&hp[c] = *(uint4*)&hbuf[c];
        }
    }
}

// ---------------- GEMM2 (tensor core): g_h2h @ W2h -> g_g2h + fused alpha2 ----------------
__global__ __launch_bounds__(256) void k_gemm2(const float* __restrict__ a2s,
                                               const float* __restrict__ a2d) {
    const int BM = 128, BN = 64, BK = 32;
    const int LDA = BK + 8;
    const int LDB = BN + 8;
    const int LDC = BN + 8;
    __shared__ __align__(16) __half Ah[BM * LDA];
    __shared__ __align__(16) __half Bh[BK * LDB];
    __shared__ __align__(16) float  Cs[BM * LDC];

    int tid = threadIdx.x;
    int wid = tid >> 5;
    int row0 = blockIdx.x * BM;
    int wm = (wid & 3) * 32;
    int wn = (wid >> 2) * 32;

    wmma::fragment<wmma::accumulator, 16, 16, 16, float> acc[2][2];
#pragma unroll
    for (int i = 0; i < 2; i++)
#pragma unroll
        for (int j = 0; j < 2; j++)
            wmma::fill_fragment(acc[i][j], 0.0f);

    for (int k0 = 0; k0 < HC; k0 += BK) {
#pragma unroll
        for (int q = 0; q < 2; q++) {
            int li = tid * 2 + q;
            int r = li >> 2;
            int c8 = li & 3;
            int gr = row0 + r;
            if (gr > NN - 1) gr = NN - 1;
            *(uint4*)&Ah[r * LDA + c8 * 8] = *(const uint4*)&g_h2h[gr * HC + k0 + c8 * 8];
        }
        {
            int r = tid >> 3;
            int c8 = tid & 7;
            *(uint4*)&Bh[r * LDB + c8 * 8] = *(const uint4*)&g_w2h[(k0 + r) * CLSP + c8 * 8];
        }
        __syncthreads();
#pragma unroll
        for (int kk = 0; kk < BK; kk += 16) {
            wmma::fragment<wmma::matrix_a, 16, 16, 16, __half, wmma::row_major> af[2];
            wmma::fragment<wmma::matrix_b, 16, 16, 16, __half, wmma::row_major> bf[2];
#pragma unroll
            for (int i = 0; i < 2; i++)
                wmma::load_matrix_sync(af[i], &Ah[(wm + i * 16) * LDA + kk], LDA);
#pragma unroll
            for (int j = 0; j < 2; j++)
                wmma::load_matrix_sync(bf[j], &Bh[kk * LDB + wn + j * 16], LDB);
#pragma unroll
            for (int i = 0; i < 2; i++)
#pragma unroll
                for (int j = 0; j < 2; j++)
                    wmma::mma_sync(acc[i][j], af[i], bf[j], acc[i][j]);
        }
        __syncthreads();
    }

#pragma unroll
    for (int i = 0; i < 2; i++)
#pragma unroll
        for (int j = 0; j < 2; j++)
            wmma::store_matrix_sync(&Cs[(wm + i * 16) * LDC + wn + j * 16], acc[i][j],
                                    LDC, wmma::mem_row_major);
    __syncthreads();

    {
        int r = tid >> 1;
        int part = tid & 1;
        int gr = row0 + r;
        const float* crow = &Cs[r * LDC + part * 20];
        if (gr < NN) {
            float ps = 0.0f, pd = 0.0f;
#pragma unroll
            for (int c = 0; c < 20; c++) {
                float v = crow[c];
                int col = part * 20 + c;
                ps += v * a2s[col];
                pd += v * a2d[col];
            }
#pragma unroll
            for (int c = 0; c < 20; c += 2) {
                *(__half2*)&g_g2h[gr * CLS + part * 20 + c] =
                    __float22half2_rn(make_float2(crow[c], crow[c + 1]));
            }
            ps += __shfl_xor_sync(0xffffffffu, ps, 1);
            pd += __shfl_xor_sync(0xffffffffu, pd, 1);
            if (part == 0) {
                g_as2[gr] = ps;
                g_ad2[gr] = pd;
            }
        } else {
            __shfl_xor_sync(0xffffffffu, 0.0f, 1);
            __shfl_xor_sync(0xffffffffu, 0.0f, 1);
        }
    }
}

// ---------------- layer1: online softmax + fp16 gather + bias + ELU -> g_h2h ----------------
// 128 threads per dst node; warp wp covers heads 2wp, 2wp+1 (64 channels = 32 half2).
__global__ __launch_bounds__(128) void k_agg1(const float* __restrict__ b1) {
    int n = blockIdx.x;
    int wp = threadIdx.x >> 5;          // 0..3
    int lane = threadIdx.x & 31;
    int hl = lane >> 4;                 // head within pair
    int h = wp * 2 + hl;
    int el = lane & 15;                 // edge slot within 16-edge chunk
    int beg = g_rowptr[n], end = g_rowptr[n + 1];
    float ad = g_ad1[n * HEADS + h];
    const __half2* __restrict__ h1h2 = (const __half2*)g_h1h;

    float m = -INFINITY, ssum = 0.0f;
    float2 acc = make_float2(0.0f, 0.0f);
    for (int i0 = beg; i0 < end; i0 += 16) {
        int i = i0 + el;
        int sl = 0;
        float e = -INFINITY;
        if (i < end) {
            sl = g_esrc[i];
            e = lrelu(g_as1[sl * HEADS + h] + ad);
        }
        float cm = e;
#pragma unroll
        for (int o = 8; o; o >>= 1) cm = fmaxf(cm, __shfl_xor_sync(0xffffffffu, cm, o));
        float mn = fmaxf(m, cm);
        float sc = __expf(m - mn);
        acc.x *= sc; acc.y *= sc; ssum *= sc;
        m = mn;
        float w = (i < end) ? __expf(e - mn) : 0.0f;
        float ws = w;
#pragma unroll
        for (int o = 8; o; o >>= 1) ws += __shfl_xor_sync(0xffffffffu, ws, o);
        ssum += ws;
        int lim = min(16, end - i0);
        for (int j = 0; j < lim; j++) {
            int   s2 = __shfl_sync(0xffffffffu, sl, j);
            float wj = __shfl_sync(0xffffffffu, w, j + (hl << 4));
            float2 v = __half22float2(h1h2[s2 * (HC / 2) + wp * 32 + lane]);
            acc.x += wj * v.x;
            acc.y += wj * v.y;
        }
    }
    int c0 = wp * 64 + lane * 2;
    float inv_s = 1.0f / ssum;
    float o0 = acc.x * inv_s + b1[c0];
    float o1 = acc.y * inv_s + b1[c0 + 1];
    o0 = (o0 > 0.0f) ? o0 : (__expf(o0) - 1.0f);
    o1 = (o1 > 0.0f) ? o1 : (__expf(o1) - 1.0f);
    *(__half2*)&g_h2h[n * HC + c0] = __float22half2_rn(make_float2(o0, o1));
}

// ---------------- layer2: online softmax + fp16 gather + bias + log_softmax ----------------
__global__ void k_agg2(const float* __restrict__ b2, float* __restrict__ out) {
    int n = blockIdx.x;
    int t = threadIdx.x;
    __shared__ float red[64];
    __shared__ int   s_src[64];
    __shared__ float s_w[64];
    __shared__ float o40[CLS];
    int beg = g_rowptr[n], end = g_rowptr[n + 1];
    float ad = g_ad2[n];
    const __half2* __restrict__ g2h2 = (const __half2*)g_g2h;

    float m = -INFINITY, ssum = 0.0f;
    float2 acc = make_float2(0.0f, 0.0f);
    for (int i0 = beg; i0 < end; i0 += 64) {
        int i = i0 + t;
        int s = 0;
        float e = -INFINITY;
        if (i < end) {
            s = g_esrc[i];
            e = lrelu(g_as2[s] + ad);
        }
        red[t] = e; __syncthreads();
        for (int off = 32; off; off >>= 1) { if (t < off) red[t] = fmaxf(red[t], red[t + off]); __syncthreads(); }
        float mn = fmaxf(m, red[0]);
        __syncthreads();
        float scale = __expf(m - mn);
        acc.x *= scale; acc.y *= scale;
        ssum *= scale;
        m = mn;
        float w = (i < end) ? __expf(e - mn) : 0.0f;
        s_src[t] = s;
        s_w[t] = w;
        red[t] = w; __syncthreads();
        for (int off = 32; off; off >>= 1) { if (t < off) red[t] += red[t + off]; __syncthreads(); }
        ssum += red[0];
        __syncthreads();
        int lim = min(64, end - i0);
        if (t < CLS / 2)
            for (int j = 0; j < lim; j++) {
                float2 v = __half22float2(g2h2[s_src[j] * (CLS / 2) + t]);
                acc.x += s_w[j] * v.x;
                acc.y += s_w[j] * v.y;
            }
        __syncthreads();
    }

    if (t < CLS / 2) {
        float inv_s = 1.0f / ssum;
        o40[t * 2]     = acc.x * inv_s + b2[t * 2];
        o40[t * 2 + 1] = acc.y * inv_s + b2[t * 2 + 1];
    }
    __syncthreads();
    float o = (t < CLS) ? o40[t] : -INFINITY;
    red[t] = o; __syncthreads();
    for (int off = 32; off; off >>= 1) { if (t < off) red[t] = fmaxf(red[t], red[t + off]); __syncthreads(); }
    float mx = red[0]; __syncthreads();
    red[t] = (t < CLS) ? __expf(o - mx) : 0.0f;
    __syncthreads();
    for (int off = 32; off; off >>= 1) { if (t < off) red[t] += red[t + off]; __syncthreads(); }
    if (t < CLS) out[n * CLS + t] = o - mx - logf(red[0]);
}

// ---------------- launch (fork/join: CSR build ∥ cvt+gemm1) ----------------
extern "C" void kernel_launch(void* const* d_in, const int* in_sizes, int n_in,
                              void* d_out, int out_size) {
    const float* x   = (const float*)d_in[0];
    const int*   ei  = (const int*)d_in[1];      // edge_index is int32 (JAX x64 disabled)
    const float* W1  = (const float*)d_in[2];
    const float* a1s = (const float*)d_in[3];
    const float* a1d = (const float*)d_in[4];
    const float* b1  = (const float*)d_in[5];
    const float* W2  = (const float*)d_in[6];
    const float* a2s = (const float*)d_in[7];
    const float* a2d = (const float*)d_in[8];
    const float* b2  = (const float*)d_in[9];
    float*       out = (float*)d_out;

    // one-time host-side objects (no device memory involved)
    static cudaStream_t s2 = nullptr;
    static cudaEvent_t eFork = nullptr, eJoin = nullptr;
    if (!s2) {
        cudaStreamCreateWithFlags(&s2, cudaStreamNonBlocking);
        cudaEventCreateWithFlags(&eFork, cudaEventDisableTiming);
        cudaEventCreateWithFlags(&eJoin, cudaEventDisableTiming);
    }

    // fork: side stream runs the CSR build (g_cnt/g_done are pre-zeroed:
    // zero-init at load, re-zeroed by k_writeptr / last k_bsum block each run)
    cudaEventRecord(eFork, 0);
    cudaStreamWaitEvent(s2, eFork, 0);

    k_count<<<(TOT / 4 + 255) / 256, 256, 0, s2>>>(ei);
    k_bsum<<<NB, 256, 0, s2>>>();
    k_writeptr<<<NB, 256, 0, s2>>>();
    k_scatter<<<(TOT + 255) / 256, 256, 0, s2>>>(ei);
    cudaEventRecord(eJoin, s2);

    // main stream: fp16 conversion + GEMM1 (independent of CSR)
    k_cvt<<<((NN * FEAT + FEAT * HC + HC * CLSP) / 2 + 255) / 256, 256>>>(x, W1, W2);
    k_gemm1<<<dim3((NN + 127) / 128, HC / 64), 256>>>(a1s, a1d);

    // join: agg1 needs both branches
    cudaStreamWaitEvent(0, eJoin, 0);
    k_agg1<<<NN, 128>>>(b1);

    // layer 2
    k_gemm2<<<(NN + 127) / 128, 256>>>(a2s, a2d);
    k_agg2<<<NN, 64>>>(b2, out);
}